// round 11
// baseline (speedup 1.0000x reference)
#include <cuda_runtime.h>
#include <cuda_bf16.h>
#include <math.h>
#include <stdint.h>

#define BATCH 16
#define SEQ   2048
#define DIM   512
#define EMB   512

// ---------------------------------------------------------------------------
// Pre-split bf16 hi/lo planes (uint32 = 2 bf16), LINEAR k-order.
// ---------------------------------------------------------------------------
__device__ uint32_t g_qh [BATCH * SEQ * DIM / 2];
__device__ uint32_t g_ql [BATCH * SEQ * DIM / 2];
__device__ uint32_t g_kh [BATCH * SEQ * DIM / 2];
__device__ uint32_t g_kl [BATCH * SEQ * DIM / 2];
__device__ uint32_t g_vh [BATCH * SEQ * DIM / 2];
__device__ uint32_t g_vl [BATCH * SEQ * DIM / 2];
__device__ uint32_t g_Wqh[EMB * DIM / 2];
__device__ uint32_t g_Wql[EMB * DIM / 2];
__device__ uint32_t g_Wkh[EMB * DIM / 2];
__device__ uint32_t g_Wkl[EMB * DIM / 2];
__device__ uint32_t g_Wvh[EMB * DIM / 2];
__device__ uint32_t g_Wvl[EMB * DIM / 2];
__device__ uint32_t g_qph[BATCH * SEQ * EMB / 2];
__device__ uint32_t g_qpl[BATCH * SEQ * EMB / 2];
__device__ uint32_t g_kph[BATCH * SEQ * EMB / 2];
__device__ uint32_t g_kpl[BATCH * SEQ * EMB / 2];
__device__ uint32_t g_vpth[BATCH * EMB * SEQ / 2];
__device__ uint32_t g_vptl[BATCH * EMB * SEQ / 2];
__device__ uint32_t g_ath[(long)BATCH * SEQ * SEQ / 2];
__device__ uint32_t g_atl[(long)BATCH * SEQ * SEQ / 2];

// ---------------------------------------------------------------------------
// helpers
// ---------------------------------------------------------------------------
__device__ __forceinline__ uint32_t pack2bf(float e0, float e1) {
    uint32_t r;
    asm("cvt.rn.bf16x2.f32 %0, %1, %2;" : "=r"(r) : "f"(e1), "f"(e0));
    return r;
}

__device__ __forceinline__ void split_pair(float x0, float x1,
                                           uint32_t& wh, uint32_t& wl) {
    wh = pack2bf(x0, x1);
    float h0 = __uint_as_float(wh << 16);
    float h1 = __uint_as_float(wh & 0xFFFF0000u);
    wl = pack2bf(x0 - h0, x1 - h1);
}

// NON-volatile: pure register computation; lets ptxas schedule freely.
__device__ __forceinline__ void mma_bf16(float* d, const uint32_t* a,
                                         const uint32_t* b) {
    asm("mma.sync.aligned.m16n8k16.row.col.f32.bf16.bf16.f32 "
        "{%0,%1,%2,%3},{%4,%5,%6,%7},{%8,%9},{%0,%1,%2,%3};"
        : "+f"(d[0]), "+f"(d[1]), "+f"(d[2]), "+f"(d[3])
        : "r"(a[0]), "r"(a[1]), "r"(a[2]), "r"(a[3]), "r"(b[0]), "r"(b[1]));
}

__device__ __forceinline__ uint32_t smem_u32(const void* p) {
    uint32_t a;
    asm("{ .reg .u64 t; cvta.to.shared.u64 t, %1; cvt.u32.u64 %0, t; }"
        : "=r"(a) : "l"(p));
    return a;
}

#define LDSM4(r0, r1, r2, r3, a) \
    asm volatile("ldmatrix.sync.aligned.m8n8.x4.shared.b16 {%0,%1,%2,%3}, [%4];" \
                 : "=r"(r0), "=r"(r1), "=r"(r2), "=r"(r3) : "r"(a))

#define CP16(dst, src) \
    asm volatile("cp.async.cg.shared.global [%0], [%1], 16;" \
                 :: "r"(dst), "l"(src) : "memory")
#define CP_COMMIT() asm volatile("cp.async.commit_group;" ::: "memory")
#define CP_WAIT1()  asm volatile("cp.async.wait_group 1;"  ::: "memory")

// ---------------------------------------------------------------------------
// one-shot conversion of all six inputs -> hi/lo bf16 planes (linear)
// ---------------------------------------------------------------------------
__global__ void __launch_bounds__(256) convert_all(
    const float* __restrict__ q, const float* __restrict__ k,
    const float* __restrict__ v, const float* __restrict__ Wq,
    const float* __restrict__ Wk, const float* __restrict__ Wv,
    uint32_t* __restrict__ qh, uint32_t* __restrict__ ql,
    uint32_t* __restrict__ kh, uint32_t* __restrict__ kl,
    uint32_t* __restrict__ vh, uint32_t* __restrict__ vl,
    uint32_t* __restrict__ Wqh, uint32_t* __restrict__ Wql,
    uint32_t* __restrict__ Wkh, uint32_t* __restrict__ Wkl,
    uint32_t* __restrict__ Wvh, uint32_t* __restrict__ Wvl,
    long inWords, long wWords)
{
    long w = (long)blockIdx.x * 256 + threadIdx.x;
    const float* src;
    uint32_t *hi, *lo;
    long idx;
    if (w < 3 * inWords) {
        int sel = (int)(w / inWords);
        idx = w - (long)sel * inWords;
        src = sel == 0 ? q : sel == 1 ? k : v;
        hi  = sel == 0 ? qh : sel == 1 ? kh : vh;
        lo  = sel == 0 ? ql : sel == 1 ? kl : vl;
    } else {
        long w2 = w - 3 * inWords;
        if (w2 >= 3 * wWords) return;
        int sel = (int)(w2 / wWords);
        idx = w2 - (long)sel * wWords;
        src = sel == 0 ? Wq : sel == 1 ? Wk : Wv;
        hi  = sel == 0 ? Wqh : sel == 1 ? Wkh : Wvh;
        lo  = sel == 0 ? Wql : sel == 1 ? Wkl : Wvl;
    }
    float2 val = *(const float2*)(src + 2 * idx);
    uint32_t wh2, wl2;
    split_pair(val.x, val.y, wh2, wl2);
    hi[idx] = wh2;
    lo[idx] = wl2;
}

// ---------------------------------------------------------------------------
// GEMM: C = alpha * A @ B^T on pre-split planes (3-mma bf16 split: hh,hl,lh).
// CTA tile 128(M) x 256(N), BK=32, 8 warps (2x4), 64x64 warp tiles,
// cp.async 3-stage pipeline, ldmatrix fragment loads, 1 sync/stage.
// Inner loop is TERM-MAJOR: all hh mmas, then all hl, then all lh so that
// mmas hitting the same accumulator are ~32 issues apart (no latency chains).
// EPI 0: f32 C.  EPI 1: linear split planes Ch/Cl.
// EPI 2: TRANSPOSED split planes (vpt layout [B][EMB][SEQ/2]), smem-staged.
// ---------------------------------------------------------------------------
#define SROW     20
#define A_PL     (128 * SROW)            // 2560 words
#define B_PL     (256 * SROW)            // 5120 words
#define STAGE_W  (2 * A_PL + 2 * B_PL)   // 15360 words
#define SMEM_BYTES (3 * STAGE_W * 4)     // 184320 B  (>= 256*130*4 for EPI=2)

template <int EPI>
__global__ void __launch_bounds__(256) gemm_bs(
    const uint32_t* __restrict__ Ah, const uint32_t* __restrict__ Al,
    const uint32_t* __restrict__ Bh, const uint32_t* __restrict__ Bl,
    float* __restrict__ C, uint32_t* __restrict__ Ch, uint32_t* __restrict__ Cl,
    int M, int Nn, int K, float alpha, long sA, long sB, long sC)
{
    extern __shared__ uint32_t sm[];

    const int tid  = threadIdx.x;
    const int lane = tid & 31;
    const int warp = tid >> 5;
    const int gid  = lane >> 2;
    const int tig  = lane & 3;
    const int wr   = warp & 1;     // 2 warp-rows (64 rows each)
    const int wc   = warp >> 1;    // 4 warp-cols (64 cols each)
    const int lm8  = lane & 7;     // ldmatrix: row within 8x8 tile
    const int ts   = lane >> 3;    // ldmatrix: tile selector 0..3

    const int KW = K >> 1;
    Ah += (long)blockIdx.z * sA;  Al += (long)blockIdx.z * sA;
    Bh += (long)blockIdx.z * sB;  Bl += (long)blockIdx.z * sB;
    C  += (long)blockIdx.z * sC;
    const int rowBase = blockIdx.y * 128;
    const int colBase = blockIdx.x * 256;

    // cp.async loaders (linear k copy)
    const int lrow = tid >> 1;            // 0..127
    const int kh   = tid & 1;             // 8-word half
    const uint32_t* gAh  = Ah + (long)(rowBase + lrow) * KW + 8 * kh;
    const uint32_t* gAl  = Al + (long)(rowBase + lrow) * KW + 8 * kh;
    const uint32_t* gB1h = Bh + (long)(colBase + lrow) * KW + 8 * kh;
    const uint32_t* gB1l = Bl + (long)(colBase + lrow) * KW + 8 * kh;
    const uint32_t* gB2h = Bh + (long)(colBase + lrow + 128) * KW + 8 * kh;
    const uint32_t* gB2l = Bl + (long)(colBase + lrow + 128) * KW + 8 * kh;

    const int spA  = lrow * SROW + 8 * kh;
    const int spB1 = lrow * SROW + 8 * kh;
    const int spB2 = (lrow + 128) * SROW + 8 * kh;

    const uint32_t smb = smem_u32(sm);

    auto issue_stage = [&](int s) {
        const uint32_t bb = smb + ((s % 3) * STAGE_W) * 4;
        const long o = (long)s * 16;
        CP16(bb + spA * 4,                gAh + o);
        CP16(bb + (spA + 4) * 4,          gAh + o + 4);
        CP16(bb + (A_PL + spA) * 4,       gAl + o);
        CP16(bb + (A_PL + spA + 4) * 4,   gAl + o + 4);
        const uint32_t bh0 = bb + (2 * A_PL) * 4;
        const uint32_t bl0 = bb + (2 * A_PL + B_PL) * 4;
        CP16(bh0 + spB1 * 4,       gB1h + o);
        CP16(bh0 + (spB1 + 4) * 4, gB1h + o + 4);
        CP16(bh0 + spB2 * 4,       gB2h + o);
        CP16(bh0 + (spB2 + 4) * 4, gB2h + o + 4);
        CP16(bl0 + spB1 * 4,       gB1l + o);
        CP16(bl0 + (spB1 + 4) * 4, gB1l + o + 4);
        CP16(bl0 + spB2 * 4,       gB2l + o);
        CP16(bl0 + (spB2 + 4) * 4, gB2l + o + 4);
    };

    // ldmatrix per-lane base byte-offsets (within a stage)
    uint32_t aBase[4];
#pragma unroll
    for (int mi = 0; mi < 4; mi++)
        aBase[mi] = ((wr * 64 + mi * 16 + ((ts & 1) << 3) + lm8) * SROW +
                     (ts >> 1) * 4) * 4;
    uint32_t bBase[4];
#pragma unroll
    for (int p = 0; p < 4; p++)
        bBase[p] = ((wc * 64 + p * 16 + ((ts >> 1) << 3) + lm8) * SROW +
                    (ts & 1) * 4) * 4;

    float acc[4][8][4];
#pragma unroll
    for (int i = 0; i < 4; i++)
#pragma unroll
        for (int j = 0; j < 8; j++)
#pragma unroll
            for (int r = 0; r < 4; r++) acc[i][j][r] = 0.f;

    const int NS = K / 32;
    issue_stage(0); CP_COMMIT();
    issue_stage(1); CP_COMMIT();

    for (int s = 0; s < NS; s++) {
        CP_WAIT1();
        __syncthreads();   // stage s ready; all warps done with stage s-1

        if (s + 2 < NS) issue_stage(s + 2);
        CP_COMMIT();

        const uint32_t stb = smb + (s % 3) * STAGE_W * 4;

#pragma unroll
        for (int kk = 0; kk < 2; kk++) {
            // ---- load ALL fragments for this k16 step ----
            uint32_t af[4][2][4];
#pragma unroll
            for (int mi = 0; mi < 4; mi++)
#pragma unroll
                for (int h = 0; h < 2; h++) {
                    const uint32_t ad = stb + h * (A_PL * 4) + aBase[mi] + kk * 32;
                    LDSM4(af[mi][h][0], af[mi][h][1], af[mi][h][2], af[mi][h][3], ad);
                }
            uint32_t bfh[4][4], bfl[4][4];
#pragma unroll
            for (int p = 0; p < 4; p++) {
                const uint32_t bhA = stb + (2 * A_PL) * 4 + bBase[p] + kk * 32;
                LDSM4(bfh[p][0], bfh[p][1], bfh[p][2], bfh[p][3], bhA);
                LDSM4(bfl[p][0], bfl[p][1], bfl[p][2], bfl[p][3], bhA + B_PL * 4);
            }
            // ---- term-major mma issue: 32 independent per term ----
#pragma unroll
            for (int p = 0; p < 4; p++)         // hh
#pragma unroll
                for (int mi = 0; mi < 4; mi++) {
                    mma_bf16(acc[mi][2 * p],     af[mi][0], bfh[p]);
                    mma_bf16(acc[mi][2 * p + 1], af[mi][0], bfh[p] + 2);
                }
#pragma unroll
            for (int p = 0; p < 4; p++)         // hl
#pragma unroll
                for (int mi = 0; mi < 4; mi++) {
                    mma_bf16(acc[mi][2 * p],     af[mi][0], bfl[p]);
                    mma_bf16(acc[mi][2 * p + 1], af[mi][0], bfl[p] + 2);
                }
#pragma unroll
            for (int p = 0; p < 4; p++)         // lh
#pragma unroll
                for (int mi = 0; mi < 4; mi++) {
                    mma_bf16(acc[mi][2 * p],     af[mi][1], bfh[p]);
                    mma_bf16(acc[mi][2 * p + 1], af[mi][1], bfh[p] + 2);
                }
        }
    }

    if (EPI == 0) {
#pragma unroll
        for (int mi = 0; mi < 4; mi++) {
            const int r = rowBase + wr * 64 + mi * 16 + gid;
#pragma unroll
            for (int ni = 0; ni < 8; ni++) {
                const int cc = colBase + wc * 64 + ni * 8 + 2 * tig;
                float2 v0 = make_float2(acc[mi][ni][0] * alpha, acc[mi][ni][1] * alpha);
                float2 v1 = make_float2(acc[mi][ni][2] * alpha, acc[mi][ni][3] * alpha);
                *(float2*)(C + (long)r * Nn + cc)       = v0;
                *(float2*)(C + (long)(r + 8) * Nn + cc) = v1;
            }
        }
    } else if (EPI == 1) {
        // linear split-plane outputs (z-grid must be 1)
        const int KWo = Nn >> 1;
#pragma unroll
        for (int mi = 0; mi < 4; mi++) {
            const int r = rowBase + wr * 64 + mi * 16 + gid;
#pragma unroll
            for (int ni = 0; ni < 8; ni++) {
                const long o = (long)(colBase >> 1) + wc * 32 + ni * 4 + tig;
                uint32_t wh, wl;
                split_pair(acc[mi][ni][0] * alpha, acc[mi][ni][1] * alpha, wh, wl);
                Ch[(long)r * KWo + o] = wh;
                Cl[(long)r * KWo + o] = wl;
                split_pair(acc[mi][ni][2] * alpha, acc[mi][ni][3] * alpha, wh, wl);
                Ch[(long)(r + 8) * KWo + o] = wh;
                Cl[(long)(r + 8) * KWo + o] = wl;
            }
        }
    } else {
        // EPI == 2: transposed split planes, layout [B][EMB][SEQ/2 words].
        __syncthreads();               // everyone done reading stage buffers
        float* T = (float*)sm;
        const int TS = 130;
#pragma unroll
        for (int mi = 0; mi < 4; mi++) {
            const int r = wr * 64 + mi * 16 + gid;
#pragma unroll
            for (int ni = 0; ni < 8; ni++) {
                const int cc = wc * 64 + ni * 8 + 2 * tig;
                T[cc * TS + r]           = acc[mi][ni][0] * alpha;
                T[(cc + 1) * TS + r]     = acc[mi][ni][1] * alpha;
                T[cc * TS + r + 8]       = acc[mi][ni][2] * alpha;
                T[(cc + 1) * TS + r + 8] = acc[mi][ni][3] * alpha;
            }
        }
        __syncthreads();
        const int b  = rowBase / SEQ;
        const int n0 = rowBase - b * SEQ;
        const int cl = tid >> 6;        // 0..3
        const int rw = tid & 63;        // 0..63
#pragma unroll 4
        for (int cc = cl; cc < 256; cc += 4) {
            float x0 = T[cc * TS + 2 * rw];
            float x1 = T[cc * TS + 2 * rw + 1];
            uint32_t wh, wl;
            split_pair(x0, x1, wh, wl);
            const long o = ((long)b * EMB + colBase + cc) * (SEQ / 2) +
                           (n0 >> 1) + rw;
            Ch[o] = wh;
            Cl[o] = wl;
        }
    }
}

// ---------------------------------------------------------------------------
// Row softmax (in place on f32) + linear bf16 split side outputs
// ---------------------------------------------------------------------------
__global__ void __launch_bounds__(256) softmax_rows(
    float* __restrict__ attn, uint32_t* __restrict__ hi,
    uint32_t* __restrict__ lo)
{
    const long row = blockIdx.x;
    float* p = attn + row * SEQ;
    uint32_t* hb = hi + row * (SEQ / 2);
    uint32_t* lb = lo + row * (SEQ / 2);
    const int tid = threadIdx.x;
    __shared__ float red[256];

    float2 vals[4];
    float lmax = -INFINITY;
#pragma unroll
    for (int i = 0; i < 4; i++) {
        vals[i] = *(const float2*)(p + 2 * (tid + i * 256));
        lmax = fmaxf(lmax, fmaxf(vals[i].x, vals[i].y));
    }
    red[tid] = lmax;
    __syncthreads();
    for (int s = 128; s > 0; s >>= 1) {
        if (tid < s) red[tid] = fmaxf(red[tid], red[tid + s]);
        __syncthreads();
    }
    const float m = red[0];
    __syncthreads();

    float lsum = 0.f;
#pragma unroll
    for (int i = 0; i < 4; i++) {
        vals[i].x = __expf(vals[i].x - m);
        vals[i].y = __expf(vals[i].y - m);
        lsum += vals[i].x + vals[i].y;
    }
    red[tid] = lsum;
    __syncthreads();
    for (int s = 128; s > 0; s >>= 1) {
        if (tid < s) red[tid] += red[tid + s];
        __syncthreads();
    }
    const float inv = 1.f / red[0];
#pragma unroll
    for (int i = 0; i < 4; i++) {
        const int w = tid + i * 256;
        float2 o = make_float2(vals[i].x * inv, vals[i].y * inv);
        *(float2*)(p + 2 * w) = o;
        uint32_t wh, wl;
        split_pair(o.x, o.y, wh, wl);
        hb[w] = wh;
        lb[w] = wl;
    }
}

// ---------------------------------------------------------------------------
extern "C" void kernel_launch(void* const* d_in, const int* in_sizes, int n_in,
                              void* d_out, int out_size)
{
    const float* q  = (const float*)d_in[0];
    const float* k  = (const float*)d_in[1];
    const float* v  = (const float*)d_in[2];
    const float* Wq = (const float*)d_in[3];
    const float* Wk = (const float*)d_in[4];
    const float* Wv = (const float*)d_in[5];

    float* out  = (float*)d_out;                  // [B, N, E]
    float* attn = out + (long)BATCH * SEQ * EMB;  // [B, N, N]

    uint32_t *qh, *ql, *kh, *kl, *vh, *vl;
    uint32_t *Wqh, *Wql, *Wkh, *Wkl, *Wvh, *Wvl;
    uint32_t *qph, *qpl, *kph, *kpl, *vpth, *vptl, *ath, *atl;
    cudaGetSymbolAddress((void**)&qh,  g_qh);   cudaGetSymbolAddress((void**)&ql,  g_ql);
    cudaGetSymbolAddress((void**)&kh,  g_kh);   cudaGetSymbolAddress((void**)&kl,  g_kl);
    cudaGetSymbolAddress((void**)&vh,  g_vh);   cudaGetSymbolAddress((void**)&vl,  g_vl);
    cudaGetSymbolAddress((void**)&Wqh, g_Wqh);  cudaGetSymbolAddress((void**)&Wql, g_Wql);
    cudaGetSymbolAddress((void**)&Wkh, g_Wkh);  cudaGetSymbolAddress((void**)&Wkl, g_Wkl);
    cudaGetSymbolAddress((void**)&Wvh, g_Wvh);  cudaGetSymbolAddress((void**)&Wvl, g_Wvl);
    cudaGetSymbolAddress((void**)&qph, g_qph);  cudaGetSymbolAddress((void**)&qpl, g_qpl);
    cudaGetSymbolAddress((void**)&kph, g_kph);  cudaGetSymbolAddress((void**)&kpl, g_kpl);
    cudaGetSymbolAddress((void**)&vpth, g_vpth); cudaGetSymbolAddress((void**)&vptl, g_vptl);
    cudaGetSymbolAddress((void**)&ath, g_ath);  cudaGetSymbolAddress((void**)&atl, g_atl);

    cudaFuncSetAttribute(gemm_bs<0>, cudaFuncAttributeMaxDynamicSharedMemorySize, SMEM_BYTES);
    cudaFuncSetAttribute(gemm_bs<1>, cudaFuncAttributeMaxDynamicSharedMemorySize, SMEM_BYTES);
    cudaFuncSetAttribute(gemm_bs<2>, cudaFuncAttributeMaxDynamicSharedMemorySize, SMEM_BYTES);

    const float c = 0.044194173824159216f;  // 1/sqrt(512)

    // 1) split all inputs in one launch
    const long inWords = (long)BATCH * SEQ * DIM / 2;
    const long wWords  = (long)EMB * DIM / 2;
    const long totW = 3 * inWords + 3 * wWords;
    convert_all<<<(unsigned)((totW + 255) / 256), 256>>>(
        q, k, v, Wq, Wk, Wv,
        qh, ql, kh, kl, vh, vl,
        Wqh, Wql, Wkh, Wkl, Wvh, Wvl, inWords, wWords);

    // 2) projections  (M = B*N, N = EMB, K = DIM)
    dim3 gp(EMB / 256, (BATCH * SEQ) / 128, 1);
    gemm_bs<1><<<gp, 256, SMEM_BYTES>>>(qh, ql, Wqh, Wql, nullptr, qph, qpl,
                                        BATCH * SEQ, EMB, DIM, c, 0, 0, 0);
    gemm_bs<1><<<gp, 256, SMEM_BYTES>>>(kh, kl, Wkh, Wkl, nullptr, kph, kpl,
                                        BATCH * SEQ, EMB, DIM, c, 0, 0, 0);
    // v projection writes TRANSPOSED split planes directly (EPI=2)
    gemm_bs<2><<<gp, 256, SMEM_BYTES>>>(vh, vl, Wvh, Wvl, nullptr, vpth, vptl,
                                        BATCH * SEQ, EMB, DIM, c, 0, 0, 0);

    // 3) dots = qp @ kp^T * c -> attn (f32)
    dim3 gd(SEQ / 256, SEQ / 128, BATCH);
    gemm_bs<0><<<gd, 256, SMEM_BYTES>>>(qph, qpl, kph, kpl, attn, nullptr, nullptr,
                                        SEQ, SEQ, EMB, c,
                                        (long)SEQ * EMB / 2, (long)SEQ * EMB / 2,
                                        (long)SEQ * SEQ);

    // 4) softmax (f32 in place + split planes)
    softmax_rows<<<BATCH * SEQ, 256>>>(attn, ath, atl);

    // 5) out = attn @ vpt^T
    dim3 go(EMB / 256, SEQ / 128, BATCH);
    gemm_bs<0><<<go, 256, SMEM_BYTES>>>(ath, atl, vpth, vptl, out, nullptr, nullptr,
                                        SEQ, EMB, SEQ, 1.0f,
                                        (long)SEQ * SEQ / 2, (long)SEQ * EMB / 2,
                                        (long)SEQ * EMB);
}

// round 12
// speedup vs baseline: 1.5337x; 1.5337x over previous
#include <cuda_runtime.h>
#include <cuda_bf16.h>
#include <math.h>
#include <stdint.h>

#define BATCH 16
#define SEQ   2048
#define DIM   512
#define EMB   512

// ---------------------------------------------------------------------------
// Pre-split bf16 hi/lo planes (uint32 = 2 bf16), LINEAR k-order.
// ---------------------------------------------------------------------------
__device__ uint32_t g_qh [BATCH * SEQ * DIM / 2];
__device__ uint32_t g_ql [BATCH * SEQ * DIM / 2];
__device__ uint32_t g_kh [BATCH * SEQ * DIM / 2];
__device__ uint32_t g_kl [BATCH * SEQ * DIM / 2];
__device__ uint32_t g_vh [BATCH * SEQ * DIM / 2];
__device__ uint32_t g_vl [BATCH * SEQ * DIM / 2];
__device__ uint32_t g_Wqh[EMB * DIM / 2];
__device__ uint32_t g_Wql[EMB * DIM / 2];
__device__ uint32_t g_Wkh[EMB * DIM / 2];
__device__ uint32_t g_Wkl[EMB * DIM / 2];
__device__ uint32_t g_Wvh[EMB * DIM / 2];
__device__ uint32_t g_Wvl[EMB * DIM / 2];
__device__ uint32_t g_qph[BATCH * SEQ * EMB / 2];
__device__ uint32_t g_qpl[BATCH * SEQ * EMB / 2];
__device__ uint32_t g_kph[BATCH * SEQ * EMB / 2];
__device__ uint32_t g_kpl[BATCH * SEQ * EMB / 2];
__device__ uint32_t g_vpth[BATCH * EMB * SEQ / 2];
__device__ uint32_t g_vptl[BATCH * EMB * SEQ / 2];
__device__ uint32_t g_ath[(long)BATCH * SEQ * SEQ / 2];
__device__ uint32_t g_atl[(long)BATCH * SEQ * SEQ / 2];

// ---------------------------------------------------------------------------
// helpers
// ---------------------------------------------------------------------------
__device__ __forceinline__ uint32_t pack2bf(float e0, float e1) {
    uint32_t r;
    asm("cvt.rn.bf16x2.f32 %0, %1, %2;" : "=r"(r) : "f"(e1), "f"(e0));
    return r;
}

__device__ __forceinline__ void split_pair(float x0, float x1,
                                           uint32_t& wh, uint32_t& wl) {
    wh = pack2bf(x0, x1);
    float h0 = __uint_as_float(wh << 16);
    float h1 = __uint_as_float(wh & 0xFFFF0000u);
    wl = pack2bf(x0 - h0, x1 - h1);
}

// volatile, consumed per-p: round-10 proven schedule
__device__ __forceinline__ void mma_bf16(float* d, const uint32_t* a,
                                         const uint32_t* b) {
    asm volatile(
        "mma.sync.aligned.m16n8k16.row.col.f32.bf16.bf16.f32 "
        "{%0,%1,%2,%3},{%4,%5,%6,%7},{%8,%9},{%0,%1,%2,%3};"
        : "+f"(d[0]), "+f"(d[1]), "+f"(d[2]), "+f"(d[3])
        : "r"(a[0]), "r"(a[1]), "r"(a[2]), "r"(a[3]), "r"(b[0]), "r"(b[1]));
}

__device__ __forceinline__ uint32_t smem_u32(const void* p) {
    uint32_t a;
    asm("{ .reg .u64 t; cvta.to.shared.u64 t, %1; cvt.u32.u64 %0, t; }"
        : "=r"(a) : "l"(p));
    return a;
}

#define LDSM4(r0, r1, r2, r3, a) \
    asm volatile("ldmatrix.sync.aligned.m8n8.x4.shared.b16 {%0,%1,%2,%3}, [%4];" \
                 : "=r"(r0), "=r"(r1), "=r"(r2), "=r"(r3) : "r"(a))

#define CP16(dst, src) \
    asm volatile("cp.async.cg.shared.global [%0], [%1], 16;" \
                 :: "r"(dst), "l"(src) : "memory")
#define CP_COMMIT() asm volatile("cp.async.commit_group;" ::: "memory")
#define CP_WAIT1()  asm volatile("cp.async.wait_group 1;"  ::: "memory")

// ---------------------------------------------------------------------------
// one-shot conversion of all six inputs -> hi/lo bf16 planes (linear)
// ---------------------------------------------------------------------------
__global__ void __launch_bounds__(256) convert_all(
    const float* __restrict__ q, const float* __restrict__ k,
    const float* __restrict__ v, const float* __restrict__ Wq,
    const float* __restrict__ Wk, const float* __restrict__ Wv,
    uint32_t* __restrict__ qh, uint32_t* __restrict__ ql,
    uint32_t* __restrict__ kh, uint32_t* __restrict__ kl,
    uint32_t* __restrict__ vh, uint32_t* __restrict__ vl,
    uint32_t* __restrict__ Wqh, uint32_t* __restrict__ Wql,
    uint32_t* __restrict__ Wkh, uint32_t* __restrict__ Wkl,
    uint32_t* __restrict__ Wvh, uint32_t* __restrict__ Wvl,
    long inWords, long wWords)
{
    long w = (long)blockIdx.x * 256 + threadIdx.x;
    const float* src;
    uint32_t *hi, *lo;
    long idx;
    if (w < 3 * inWords) {
        int sel = (int)(w / inWords);
        idx = w - (long)sel * inWords;
        src = sel == 0 ? q : sel == 1 ? k : v;
        hi  = sel == 0 ? qh : sel == 1 ? kh : vh;
        lo  = sel == 0 ? ql : sel == 1 ? kl : vl;
    } else {
        long w2 = w - 3 * inWords;
        if (w2 >= 3 * wWords) return;
        int sel = (int)(w2 / wWords);
        idx = w2 - (long)sel * wWords;
        src = sel == 0 ? Wq : sel == 1 ? Wk : Wv;
        hi  = sel == 0 ? Wqh : sel == 1 ? Wkh : Wvh;
        lo  = sel == 0 ? Wql : sel == 1 ? Wkl : Wvl;
    }
    float2 val = *(const float2*)(src + 2 * idx);
    uint32_t wh2, wl2;
    split_pair(val.x, val.y, wh2, wl2);
    hi[idx] = wh2;
    lo[idx] = wl2;
}

// ---------------------------------------------------------------------------
// GEMM: C = alpha * A @ B^T on pre-split planes (3-mma bf16 split: hh,hl,lh).
// CTA tile 128(M) x 256(N), BK=32, 8 warps (2x4), 64x64 warp tiles,
// cp.async 3-stage pipeline, ldmatrix fragment loads, 1 sync/stage.
// (round-10 proven inner loop: B-fragments consumed per-p)
// EPI 0: f32 C.  EPI 1: linear split planes Ch/Cl.
// EPI 2: TRANSPOSED split planes (vpt layout [B][EMB][SEQ/2]), smem-staged.
// ---------------------------------------------------------------------------
#define SROW     20
#define A_PL     (128 * SROW)            // 2560 words
#define B_PL     (256 * SROW)            // 5120 words
#define STAGE_W  (2 * A_PL + 2 * B_PL)   // 15360 words
#define SMEM_BYTES (3 * STAGE_W * 4)     // 184320 B  (>= 256*130*4 for EPI=2)

template <int EPI>
__global__ void __launch_bounds__(256) gemm_bs(
    const uint32_t* __restrict__ Ah, const uint32_t* __restrict__ Al,
    const uint32_t* __restrict__ Bh, const uint32_t* __restrict__ Bl,
    float* __restrict__ C, uint32_t* __restrict__ Ch, uint32_t* __restrict__ Cl,
    int M, int Nn, int K, float alpha, long sA, long sB, long sC)
{
    extern __shared__ uint32_t sm[];

    const int tid  = threadIdx.x;
    const int lane = tid & 31;
    const int warp = tid >> 5;
    const int gid  = lane >> 2;
    const int tig  = lane & 3;
    const int wr   = warp & 1;     // 2 warp-rows (64 rows each)
    const int wc   = warp >> 1;    // 4 warp-cols (64 cols each)
    const int lm8  = lane & 7;     // ldmatrix: row within 8x8 tile
    const int ts   = lane >> 3;    // ldmatrix: tile selector 0..3

    const int KW = K >> 1;
    Ah += (long)blockIdx.z * sA;  Al += (long)blockIdx.z * sA;
    Bh += (long)blockIdx.z * sB;  Bl += (long)blockIdx.z * sB;
    C  += (long)blockIdx.z * sC;
    const int rowBase = blockIdx.y * 128;
    const int colBase = blockIdx.x * 256;

    // cp.async loaders (linear k copy)
    const int lrow = tid >> 1;            // 0..127
    const int kh   = tid & 1;             // 8-word half
    const uint32_t* gAh  = Ah + (long)(rowBase + lrow) * KW + 8 * kh;
    const uint32_t* gAl  = Al + (long)(rowBase + lrow) * KW + 8 * kh;
    const uint32_t* gB1h = Bh + (long)(colBase + lrow) * KW + 8 * kh;
    const uint32_t* gB1l = Bl + (long)(colBase + lrow) * KW + 8 * kh;
    const uint32_t* gB2h = Bh + (long)(colBase + lrow + 128) * KW + 8 * kh;
    const uint32_t* gB2l = Bl + (long)(colBase + lrow + 128) * KW + 8 * kh;

    const int spA  = lrow * SROW + 8 * kh;
    const int spB1 = lrow * SROW + 8 * kh;
    const int spB2 = (lrow + 128) * SROW + 8 * kh;

    const uint32_t smb = smem_u32(sm);

    auto issue_stage = [&](int s) {
        const uint32_t bb = smb + ((s % 3) * STAGE_W) * 4;
        const long o = (long)s * 16;
        CP16(bb + spA * 4,                gAh + o);
        CP16(bb + (spA + 4) * 4,          gAh + o + 4);
        CP16(bb + (A_PL + spA) * 4,       gAl + o);
        CP16(bb + (A_PL + spA + 4) * 4,   gAl + o + 4);
        const uint32_t bh0 = bb + (2 * A_PL) * 4;
        const uint32_t bl0 = bb + (2 * A_PL + B_PL) * 4;
        CP16(bh0 + spB1 * 4,       gB1h + o);
        CP16(bh0 + (spB1 + 4) * 4, gB1h + o + 4);
        CP16(bh0 + spB2 * 4,       gB2h + o);
        CP16(bh0 + (spB2 + 4) * 4, gB2h + o + 4);
        CP16(bl0 + spB1 * 4,       gB1l + o);
        CP16(bl0 + (spB1 + 4) * 4, gB1l + o + 4);
        CP16(bl0 + spB2 * 4,       gB2l + o);
        CP16(bl0 + (spB2 + 4) * 4, gB2l + o + 4);
    };

    // ldmatrix per-lane base byte-offsets (within a stage)
    uint32_t aBase[4];
#pragma unroll
    for (int mi = 0; mi < 4; mi++)
        aBase[mi] = ((wr * 64 + mi * 16 + ((ts & 1) << 3) + lm8) * SROW +
                     (ts >> 1) * 4) * 4;
    uint32_t bBase[4];
#pragma unroll
    for (int p = 0; p < 4; p++)
        bBase[p] = ((wc * 64 + p * 16 + ((ts >> 1) << 3) + lm8) * SROW +
                    (ts & 1) * 4) * 4;

    float acc[4][8][4];
#pragma unroll
    for (int i = 0; i < 4; i++)
#pragma unroll
        for (int j = 0; j < 8; j++)
#pragma unroll
            for (int r = 0; r < 4; r++) acc[i][j][r] = 0.f;

    const int NS = K / 32;
    issue_stage(0); CP_COMMIT();
    issue_stage(1); CP_COMMIT();

    for (int s = 0; s < NS; s++) {
        CP_WAIT1();
        __syncthreads();   // stage s ready; all warps done with stage s-1

        if (s + 2 < NS) issue_stage(s + 2);
        CP_COMMIT();

        const uint32_t stb = smb + (s % 3) * STAGE_W * 4;

#pragma unroll
        for (int kk = 0; kk < 2; kk++) {
            uint32_t af[4][2][4];
#pragma unroll
            for (int mi = 0; mi < 4; mi++)
#pragma unroll
                for (int h = 0; h < 2; h++) {
                    const uint32_t ad = stb + h * (A_PL * 4) + aBase[mi] + kk * 32;
                    LDSM4(af[mi][h][0], af[mi][h][1], af[mi][h][2], af[mi][h][3], ad);
                }
#pragma unroll
            for (int p = 0; p < 4; p++) {
                const uint32_t bhA = stb + (2 * A_PL) * 4 + bBase[p] + kk * 32;
                uint32_t bh[4], bl[4];
                LDSM4(bh[0], bh[1], bh[2], bh[3], bhA);
                LDSM4(bl[0], bl[1], bl[2], bl[3], bhA + B_PL * 4);
#pragma unroll
                for (int mi = 0; mi < 4; mi++) {
                    mma_bf16(acc[mi][2 * p],     af[mi][0], bh);      // hh
                    mma_bf16(acc[mi][2 * p],     af[mi][0], bl);      // hl
                    mma_bf16(acc[mi][2 * p],     af[mi][1], bh);      // lh
                    mma_bf16(acc[mi][2 * p + 1], af[mi][0], bh + 2);
                    mma_bf16(acc[mi][2 * p + 1], af[mi][0], bl + 2);
                    mma_bf16(acc[mi][2 * p + 1], af[mi][1], bh + 2);
                }
            }
        }
    }

    if (EPI == 0) {
#pragma unroll
        for (int mi = 0; mi < 4; mi++) {
            const int r = rowBase + wr * 64 + mi * 16 + gid;
#pragma unroll
            for (int ni = 0; ni < 8; ni++) {
                const int cc = colBase + wc * 64 + ni * 8 + 2 * tig;
                float2 v0 = make_float2(acc[mi][ni][0] * alpha, acc[mi][ni][1] * alpha);
                float2 v1 = make_float2(acc[mi][ni][2] * alpha, acc[mi][ni][3] * alpha);
                *(float2*)(C + (long)r * Nn + cc)       = v0;
                *(float2*)(C + (long)(r + 8) * Nn + cc) = v1;
            }
        }
    } else if (EPI == 1) {
        // linear split-plane outputs (z-grid must be 1)
        const int KWo = Nn >> 1;
#pragma unroll
        for (int mi = 0; mi < 4; mi++) {
            const int r = rowBase + wr * 64 + mi * 16 + gid;
#pragma unroll
            for (int ni = 0; ni < 8; ni++) {
                const long o = (long)(colBase >> 1) + wc * 32 + ni * 4 + tig;
                uint32_t wh, wl;
                split_pair(acc[mi][ni][0] * alpha, acc[mi][ni][1] * alpha, wh, wl);
                Ch[(long)r * KWo + o] = wh;
                Cl[(long)r * KWo + o] = wl;
                split_pair(acc[mi][ni][2] * alpha, acc[mi][ni][3] * alpha, wh, wl);
                Ch[(long)(r + 8) * KWo + o] = wh;
                Cl[(long)(r + 8) * KWo + o] = wl;
            }
        }
    } else {
        // EPI == 2: transposed split planes, layout [B][EMB][SEQ/2 words].
        __syncthreads();               // everyone done reading stage buffers
        float* T = (float*)sm;
        const int TS = 130;
#pragma unroll
        for (int mi = 0; mi < 4; mi++) {
            const int r = wr * 64 + mi * 16 + gid;
#pragma unroll
            for (int ni = 0; ni < 8; ni++) {
                const int cc = wc * 64 + ni * 8 + 2 * tig;
                T[cc * TS + r]           = acc[mi][ni][0] * alpha;
                T[(cc + 1) * TS + r]     = acc[mi][ni][1] * alpha;
                T[cc * TS + r + 8]       = acc[mi][ni][2] * alpha;
                T[(cc + 1) * TS + r + 8] = acc[mi][ni][3] * alpha;
            }
        }
        __syncthreads();
        const int b  = rowBase / SEQ;
        const int n0 = rowBase - b * SEQ;
        const int cl = tid >> 6;        // 0..3
        const int rw = tid & 63;        // 0..63
#pragma unroll 4
        for (int cc = cl; cc < 256; cc += 4) {
            float x0 = T[cc * TS + 2 * rw];
            float x1 = T[cc * TS + 2 * rw + 1];
            uint32_t wh, wl;
            split_pair(x0, x1, wh, wl);
            const long o = ((long)b * EMB + colBase + cc) * (SEQ / 2) +
                           (n0 >> 1) + rw;
            Ch[o] = wh;
            Cl[o] = wl;
        }
    }
}

// ---------------------------------------------------------------------------
// Row softmax (in place on f32) + linear bf16 split side outputs.
// Warp-shuffle reductions: 2 __syncthreads total (vs 16 before).
// ---------------------------------------------------------------------------
__global__ void __launch_bounds__(256) softmax_rows(
    float* __restrict__ attn, uint32_t* __restrict__ hi,
    uint32_t* __restrict__ lo)
{
    const long row = blockIdx.x;
    float* p = attn + row * SEQ;
    uint32_t* hb = hi + row * (SEQ / 2);
    uint32_t* lb = lo + row * (SEQ / 2);
    const int tid  = threadIdx.x;
    const int lane = tid & 31;
    const int wid  = tid >> 5;
    __shared__ float red[8];

    float2 vals[4];
    float lmax = -INFINITY;
#pragma unroll
    for (int i = 0; i < 4; i++) {
        vals[i] = *(const float2*)(p + 2 * (tid + i * 256));
        lmax = fmaxf(lmax, fmaxf(vals[i].x, vals[i].y));
    }
#pragma unroll
    for (int o = 16; o > 0; o >>= 1)
        lmax = fmaxf(lmax, __shfl_xor_sync(0xFFFFFFFFu, lmax, o));
    if (lane == 0) red[wid] = lmax;
    __syncthreads();
    float m = red[0];
#pragma unroll
    for (int w = 1; w < 8; w++) m = fmaxf(m, red[w]);
    __syncthreads();   // protect red[] before reuse for the sum

    float lsum = 0.f;
#pragma unroll
    for (int i = 0; i < 4; i++) {
        vals[i].x = __expf(vals[i].x - m);
        vals[i].y = __expf(vals[i].y - m);
        lsum += vals[i].x + vals[i].y;
    }
#pragma unroll
    for (int o = 16; o > 0; o >>= 1)
        lsum += __shfl_xor_sync(0xFFFFFFFFu, lsum, o);
    if (lane == 0) red[wid] = lsum;
    __syncthreads();
    float tot = red[0];
#pragma unroll
    for (int w = 1; w < 8; w++) tot += red[w];

    const float inv = 1.f / tot;
#pragma unroll
    for (int i = 0; i < 4; i++) {
        const int w = tid + i * 256;
        float2 o2 = make_float2(vals[i].x * inv, vals[i].y * inv);
        *(float2*)(p + 2 * w) = o2;
        uint32_t wh, wl;
        split_pair(o2.x, o2.y, wh, wl);
        hb[w] = wh;
        lb[w] = wl;
    }
}

// ---------------------------------------------------------------------------
extern "C" void kernel_launch(void* const* d_in, const int* in_sizes, int n_in,
                              void* d_out, int out_size)
{
    const float* q  = (const float*)d_in[0];
    const float* k  = (const float*)d_in[1];
    const float* v  = (const float*)d_in[2];
    const float* Wq = (const float*)d_in[3];
    const float* Wk = (const float*)d_in[4];
    const float* Wv = (const float*)d_in[5];

    float* out  = (float*)d_out;                  // [B, N, E]
    float* attn = out + (long)BATCH * SEQ * EMB;  // [B, N, N]

    uint32_t *qh, *ql, *kh, *kl, *vh, *vl;
    uint32_t *Wqh, *Wql, *Wkh, *Wkl, *Wvh, *Wvl;
    uint32_t *qph, *qpl, *kph, *kpl, *vpth, *vptl, *ath, *atl;
    cudaGetSymbolAddress((void**)&qh,  g_qh);   cudaGetSymbolAddress((void**)&ql,  g_ql);
    cudaGetSymbolAddress((void**)&kh,  g_kh);   cudaGetSymbolAddress((void**)&kl,  g_kl);
    cudaGetSymbolAddress((void**)&vh,  g_vh);   cudaGetSymbolAddress((void**)&vl,  g_vl);
    cudaGetSymbolAddress((void**)&Wqh, g_Wqh);  cudaGetSymbolAddress((void**)&Wql, g_Wql);
    cudaGetSymbolAddress((void**)&Wkh, g_Wkh);  cudaGetSymbolAddress((void**)&Wkl, g_Wkl);
    cudaGetSymbolAddress((void**)&Wvh, g_Wvh);  cudaGetSymbolAddress((void**)&Wvl, g_Wvl);
    cudaGetSymbolAddress((void**)&qph, g_qph);  cudaGetSymbolAddress((void**)&qpl, g_qpl);
    cudaGetSymbolAddress((void**)&kph, g_kph);  cudaGetSymbolAddress((void**)&kpl, g_kpl);
    cudaGetSymbolAddress((void**)&vpth, g_vpth); cudaGetSymbolAddress((void**)&vptl, g_vptl);
    cudaGetSymbolAddress((void**)&ath, g_ath);  cudaGetSymbolAddress((void**)&atl, g_atl);

    cudaFuncSetAttribute(gemm_bs<0>, cudaFuncAttributeMaxDynamicSharedMemorySize, SMEM_BYTES);
    cudaFuncSetAttribute(gemm_bs<1>, cudaFuncAttributeMaxDynamicSharedMemorySize, SMEM_BYTES);
    cudaFuncSetAttribute(gemm_bs<2>, cudaFuncAttributeMaxDynamicSharedMemorySize, SMEM_BYTES);

    const float c = 0.044194173824159216f;  // 1/sqrt(512)

    // 1) split all inputs in one launch
    const long inWords = (long)BATCH * SEQ * DIM / 2;
    const long wWords  = (long)EMB * DIM / 2;
    const long totW = 3 * inWords + 3 * wWords;
    convert_all<<<(unsigned)((totW + 255) / 256), 256>>>(
        q, k, v, Wq, Wk, Wv,
        qh, ql, kh, kl, vh, vl,
        Wqh, Wql, Wkh, Wkl, Wvh, Wvl, inWords, wWords);

    // 2) projections  (M = B*N, N = EMB, K = DIM)
    dim3 gp(EMB / 256, (BATCH * SEQ) / 128, 1);
    gemm_bs<1><<<gp, 256, SMEM_BYTES>>>(qh, ql, Wqh, Wql, nullptr, qph, qpl,
                                        BATCH * SEQ, EMB, DIM, c, 0, 0, 0);
    gemm_bs<1><<<gp, 256, SMEM_BYTES>>>(kh, kl, Wkh, Wkl, nullptr, kph, kpl,
                                        BATCH * SEQ, EMB, DIM, c, 0, 0, 0);
    // v projection writes TRANSPOSED split planes directly (EPI=2)
    gemm_bs<2><<<gp, 256, SMEM_BYTES>>>(vh, vl, Wvh, Wvl, nullptr, vpth, vptl,
                                        BATCH * SEQ, EMB, DIM, c, 0, 0, 0);

    // 3) dots = qp @ kp^T * c -> attn (f32)
    dim3 gd(SEQ / 256, SEQ / 128, BATCH);
    gemm_bs<0><<<gd, 256, SMEM_BYTES>>>(qph, qpl, kph, kpl, attn, nullptr, nullptr,
                                        SEQ, SEQ, EMB, c,
                                        (long)SEQ * EMB / 2, (long)SEQ * EMB / 2,
                                        (long)SEQ * SEQ);

    // 4) softmax (f32 in place + split planes)
    softmax_rows<<<BATCH * SEQ, 256>>>(attn, ath, atl);

    // 5) out = attn @ vpt^T
    dim3 go(EMB / 256, SEQ / 128, BATCH);
    gemm_bs<0><<<go, 256, SMEM_BYTES>>>(ath, atl, vpth, vptl, out, nullptr, nullptr,
                                        SEQ, EMB, SEQ, 1.0f,
                                        (long)SEQ * SEQ / 2, (long)SEQ * EMB / 2,
                                        (long)SEQ * EMB);
}

// round 13
// speedup vs baseline: 1.5364x; 1.0017x over previous
#include <cuda_runtime.h>
#include <cuda_bf16.h>
#include <math.h>
#include <stdint.h>

#define BATCH 16
#define SEQ   2048
#define DIM   512
#define EMB   512

// ---------------------------------------------------------------------------
// Pre-split bf16 hi/lo planes (uint32 = 2 bf16), LINEAR k-order.
// ---------------------------------------------------------------------------
__device__ uint32_t g_qh [BATCH * SEQ * DIM / 2];
__device__ uint32_t g_ql [BATCH * SEQ * DIM / 2];
__device__ uint32_t g_kh [BATCH * SEQ * DIM / 2];
__device__ uint32_t g_kl [BATCH * SEQ * DIM / 2];
__device__ uint32_t g_vh [BATCH * SEQ * DIM / 2];
__device__ uint32_t g_vl [BATCH * SEQ * DIM / 2];
__device__ uint32_t g_Wqh[EMB * DIM / 2];
__device__ uint32_t g_Wql[EMB * DIM / 2];
__device__ uint32_t g_Wkh[EMB * DIM / 2];
__device__ uint32_t g_Wkl[EMB * DIM / 2];
__device__ uint32_t g_Wvh[EMB * DIM / 2];
__device__ uint32_t g_Wvl[EMB * DIM / 2];
__device__ uint32_t g_qph[BATCH * SEQ * EMB / 2];
__device__ uint32_t g_qpl[BATCH * SEQ * EMB / 2];
__device__ uint32_t g_kph[BATCH * SEQ * EMB / 2];
__device__ uint32_t g_kpl[BATCH * SEQ * EMB / 2];
__device__ uint32_t g_vpth[BATCH * EMB * SEQ / 2];
__device__ uint32_t g_vptl[BATCH * EMB * SEQ / 2];
__device__ uint32_t g_ath[(long)BATCH * SEQ * SEQ / 2];
__device__ uint32_t g_atl[(long)BATCH * SEQ * SEQ / 2];

// ---------------------------------------------------------------------------
// helpers
// ---------------------------------------------------------------------------
__device__ __forceinline__ uint32_t pack2bf(float e0, float e1) {
    uint32_t r;
    asm("cvt.rn.bf16x2.f32 %0, %1, %2;" : "=r"(r) : "f"(e1), "f"(e0));
    return r;
}

__device__ __forceinline__ void split_pair(float x0, float x1,
                                           uint32_t& wh, uint32_t& wl) {
    wh = pack2bf(x0, x1);
    float h0 = __uint_as_float(wh << 16);
    float h1 = __uint_as_float(wh & 0xFFFF0000u);
    wl = pack2bf(x0 - h0, x1 - h1);
}

// volatile: order below is exactly the issue order
__device__ __forceinline__ void mma_bf16(float* d, const uint32_t* a,
                                         const uint32_t* b) {
    asm volatile(
        "mma.sync.aligned.m16n8k16.row.col.f32.bf16.bf16.f32 "
        "{%0,%1,%2,%3},{%4,%5,%6,%7},{%8,%9},{%0,%1,%2,%3};"
        : "+f"(d[0]), "+f"(d[1]), "+f"(d[2]), "+f"(d[3])
        : "r"(a[0]), "r"(a[1]), "r"(a[2]), "r"(a[3]), "r"(b[0]), "r"(b[1]));
}

__device__ __forceinline__ uint32_t smem_u32(const void* p) {
    uint32_t a;
    asm("{ .reg .u64 t; cvta.to.shared.u64 t, %1; cvt.u32.u64 %0, t; }"
        : "=r"(a) : "l"(p));
    return a;
}

#define LDSM4(r0, r1, r2, r3, a) \
    asm volatile("ldmatrix.sync.aligned.m8n8.x4.shared.b16 {%0,%1,%2,%3}, [%4];" \
                 : "=r"(r0), "=r"(r1), "=r"(r2), "=r"(r3) : "r"(a))

#define CP16(dst, src) \
    asm volatile("cp.async.cg.shared.global [%0], [%1], 16;" \
                 :: "r"(dst), "l"(src) : "memory")
#define CP_COMMIT() asm volatile("cp.async.commit_group;" ::: "memory")
#define CP_WAIT1()  asm volatile("cp.async.wait_group 1;"  ::: "memory")

// ---------------------------------------------------------------------------
// one-shot conversion of all six inputs -> hi/lo bf16 planes (linear)
// ---------------------------------------------------------------------------
__global__ void __launch_bounds__(256) convert_all(
    const float* __restrict__ q, const float* __restrict__ k,
    const float* __restrict__ v, const float* __restrict__ Wq,
    const float* __restrict__ Wk, const float* __restrict__ Wv,
    uint32_t* __restrict__ qh, uint32_t* __restrict__ ql,
    uint32_t* __restrict__ kh, uint32_t* __restrict__ kl,
    uint32_t* __restrict__ vh, uint32_t* __restrict__ vl,
    uint32_t* __restrict__ Wqh, uint32_t* __restrict__ Wql,
    uint32_t* __restrict__ Wkh, uint32_t* __restrict__ Wkl,
    uint32_t* __restrict__ Wvh, uint32_t* __restrict__ Wvl,
    long inWords, long wWords)
{
    long w = (long)blockIdx.x * 256 + threadIdx.x;
    const float* src;
    uint32_t *hi, *lo;
    long idx;
    if (w < 3 * inWords) {
        int sel = (int)(w / inWords);
        idx = w - (long)sel * inWords;
        src = sel == 0 ? q : sel == 1 ? k : v;
        hi  = sel == 0 ? qh : sel == 1 ? kh : vh;
        lo  = sel == 0 ? ql : sel == 1 ? kl : vl;
    } else {
        long w2 = w - 3 * inWords;
        if (w2 >= 3 * wWords) return;
        int sel = (int)(w2 / wWords);
        idx = w2 - (long)sel * wWords;
        src = sel == 0 ? Wq : sel == 1 ? Wk : Wv;
        hi  = sel == 0 ? Wqh : sel == 1 ? Wkh : Wvh;
        lo  = sel == 0 ? Wql : sel == 1 ? Wkl : Wvl;
    }
    float2 val = *(const float2*)(src + 2 * idx);
    uint32_t wh2, wl2;
    split_pair(val.x, val.y, wh2, wl2);
    hi[idx] = wh2;
    lo[idx] = wl2;
}

// ---------------------------------------------------------------------------
// GEMM: C = alpha * A @ B^T on pre-split planes (3-mma bf16 split: hh,hl,lh).
// CTA tile 128(M) x 256(N), BK=32, 8 warps (2x4), 64x64 warp tiles,
// cp.async 3-stage pipeline, ldmatrix fragment loads, 1 sync/stage.
// Per-p mma order: six mi-sweeps -> same-accumulator distance 8 (latency
// hidden), with the SAME live register set as the round-10/12 schedule.
// EPI 0: f32 C.  EPI 1: linear split planes Ch/Cl.
// EPI 2: TRANSPOSED split planes (vpt layout [B][EMB][SEQ/2]), smem-staged.
// ---------------------------------------------------------------------------
#define SROW     20
#define A_PL     (128 * SROW)            // 2560 words
#define B_PL     (256 * SROW)            // 5120 words
#define STAGE_W  (2 * A_PL + 2 * B_PL)   // 15360 words
#define SMEM_BYTES (3 * STAGE_W * 4)     // 184320 B  (>= 256*130*4 for EPI=2)

template <int EPI>
__global__ void __launch_bounds__(256) gemm_bs(
    const uint32_t* __restrict__ Ah, const uint32_t* __restrict__ Al,
    const uint32_t* __restrict__ Bh, const uint32_t* __restrict__ Bl,
    float* __restrict__ C, uint32_t* __restrict__ Ch, uint32_t* __restrict__ Cl,
    int M, int Nn, int K, float alpha, long sA, long sB, long sC)
{
    extern __shared__ uint32_t sm[];

    const int tid  = threadIdx.x;
    const int lane = tid & 31;
    const int warp = tid >> 5;
    const int gid  = lane >> 2;
    const int tig  = lane & 3;
    const int wr   = warp & 1;     // 2 warp-rows (64 rows each)
    const int wc   = warp >> 1;    // 4 warp-cols (64 cols each)
    const int lm8  = lane & 7;     // ldmatrix: row within 8x8 tile
    const int ts   = lane >> 3;    // ldmatrix: tile selector 0..3

    const int KW = K >> 1;
    Ah += (long)blockIdx.z * sA;  Al += (long)blockIdx.z * sA;
    Bh += (long)blockIdx.z * sB;  Bl += (long)blockIdx.z * sB;
    C  += (long)blockIdx.z * sC;
    const int rowBase = blockIdx.y * 128;
    const int colBase = blockIdx.x * 256;

    // cp.async loaders (linear k copy)
    const int lrow = tid >> 1;            // 0..127
    const int kh   = tid & 1;             // 8-word half
    const uint32_t* gAh  = Ah + (long)(rowBase + lrow) * KW + 8 * kh;
    const uint32_t* gAl  = Al + (long)(rowBase + lrow) * KW + 8 * kh;
    const uint32_t* gB1h = Bh + (long)(colBase + lrow) * KW + 8 * kh;
    const uint32_t* gB1l = Bl + (long)(colBase + lrow) * KW + 8 * kh;
    const uint32_t* gB2h = Bh + (long)(colBase + lrow + 128) * KW + 8 * kh;
    const uint32_t* gB2l = Bl + (long)(colBase + lrow + 128) * KW + 8 * kh;

    const int spA  = lrow * SROW + 8 * kh;
    const int spB1 = lrow * SROW + 8 * kh;
    const int spB2 = (lrow + 128) * SROW + 8 * kh;

    const uint32_t smb = smem_u32(sm);

    auto issue_stage = [&](int s) {
        const uint32_t bb = smb + ((s % 3) * STAGE_W) * 4;
        const long o = (long)s * 16;
        CP16(bb + spA * 4,                gAh + o);
        CP16(bb + (spA + 4) * 4,          gAh + o + 4);
        CP16(bb + (A_PL + spA) * 4,       gAl + o);
        CP16(bb + (A_PL + spA + 4) * 4,   gAl + o + 4);
        const uint32_t bh0 = bb + (2 * A_PL) * 4;
        const uint32_t bl0 = bb + (2 * A_PL + B_PL) * 4;
        CP16(bh0 + spB1 * 4,       gB1h + o);
        CP16(bh0 + (spB1 + 4) * 4, gB1h + o + 4);
        CP16(bh0 + spB2 * 4,       gB2h + o);
        CP16(bh0 + (spB2 + 4) * 4, gB2h + o + 4);
        CP16(bl0 + spB1 * 4,       gB1l + o);
        CP16(bl0 + (spB1 + 4) * 4, gB1l + o + 4);
        CP16(bl0 + spB2 * 4,       gB2l + o);
        CP16(bl0 + (spB2 + 4) * 4, gB2l + o + 4);
    };

    // ldmatrix per-lane base byte-offsets (within a stage)
    uint32_t aBase[4];
#pragma unroll
    for (int mi = 0; mi < 4; mi++)
        aBase[mi] = ((wr * 64 + mi * 16 + ((ts & 1) << 3) + lm8) * SROW +
                     (ts >> 1) * 4) * 4;
    uint32_t bBase[4];
#pragma unroll
    for (int p = 0; p < 4; p++)
        bBase[p] = ((wc * 64 + p * 16 + ((ts >> 1) << 3) + lm8) * SROW +
                    (ts & 1) * 4) * 4;

    float acc[4][8][4];
#pragma unroll
    for (int i = 0; i < 4; i++)
#pragma unroll
        for (int j = 0; j < 8; j++)
#pragma unroll
            for (int r = 0; r < 4; r++) acc[i][j][r] = 0.f;

    const int NS = K / 32;
    issue_stage(0); CP_COMMIT();
    issue_stage(1); CP_COMMIT();

    for (int s = 0; s < NS; s++) {
        CP_WAIT1();
        __syncthreads();   // stage s ready; all warps done with stage s-1

        if (s + 2 < NS) issue_stage(s + 2);
        CP_COMMIT();

        const uint32_t stb = smb + (s % 3) * STAGE_W * 4;

#pragma unroll
        for (int kk = 0; kk < 2; kk++) {
            uint32_t af[4][2][4];
#pragma unroll
            for (int mi = 0; mi < 4; mi++)
#pragma unroll
                for (int h = 0; h < 2; h++) {
                    const uint32_t ad = stb + h * (A_PL * 4) + aBase[mi] + kk * 32;
                    LDSM4(af[mi][h][0], af[mi][h][1], af[mi][h][2], af[mi][h][3], ad);
                }
#pragma unroll
            for (int p = 0; p < 4; p++) {
                const uint32_t bhA = stb + (2 * A_PL) * 4 + bBase[p] + kk * 32;
                uint32_t bh[4], bl[4];
                LDSM4(bh[0], bh[1], bh[2], bh[3], bhA);
                LDSM4(bl[0], bl[1], bl[2], bl[3], bhA + B_PL * 4);
                // six mi-sweeps: same-accumulator distance = 8 issues
#pragma unroll
                for (int mi = 0; mi < 4; mi++)
                    mma_bf16(acc[mi][2 * p],     af[mi][0], bh);      // hh lo-n
#pragma unroll
                for (int mi = 0; mi < 4; mi++)
                    mma_bf16(acc[mi][2 * p + 1], af[mi][0], bh + 2);  // hh hi-n
#pragma unroll
                for (int mi = 0; mi < 4; mi++)
                    mma_bf16(acc[mi][2 * p],     af[mi][0], bl);      // hl lo-n
#pragma unroll
                for (int mi = 0; mi < 4; mi++)
                    mma_bf16(acc[mi][2 * p + 1], af[mi][0], bl + 2);  // hl hi-n
#pragma unroll
                for (int mi = 0; mi < 4; mi++)
                    mma_bf16(acc[mi][2 * p],     af[mi][1], bh);      // lh lo-n
#pragma unroll
                for (int mi = 0; mi < 4; mi++)
                    mma_bf16(acc[mi][2 * p + 1], af[mi][1], bh + 2);  // lh hi-n
            }
        }
    }

    if (EPI == 0) {
#pragma unroll
        for (int mi = 0; mi < 4; mi++) {
            const int r = rowBase + wr * 64 + mi * 16 + gid;
#pragma unroll
            for (int ni = 0; ni < 8; ni++) {
                const int cc = colBase + wc * 64 + ni * 8 + 2 * tig;
                float2 v0 = make_float2(acc[mi][ni][0] * alpha, acc[mi][ni][1] * alpha);
                float2 v1 = make_float2(acc[mi][ni][2] * alpha, acc[mi][ni][3] * alpha);
                *(float2*)(C + (long)r * Nn + cc)       = v0;
                *(float2*)(C + (long)(r + 8) * Nn + cc) = v1;
            }
        }
    } else if (EPI == 1) {
        // linear split-plane outputs (z-grid must be 1)
        const int KWo = Nn >> 1;
#pragma unroll
        for (int mi = 0; mi < 4; mi++) {
            const int r = rowBase + wr * 64 + mi * 16 + gid;
#pragma unroll
            for (int ni = 0; ni < 8; ni++) {
                const long o = (long)(colBase >> 1) + wc * 32 + ni * 4 + tig;
                uint32_t wh, wl;
                split_pair(acc[mi][ni][0] * alpha, acc[mi][ni][1] * alpha, wh, wl);
                Ch[(long)r * KWo + o] = wh;
                Cl[(long)r * KWo + o] = wl;
                split_pair(acc[mi][ni][2] * alpha, acc[mi][ni][3] * alpha, wh, wl);
                Ch[(long)(r + 8) * KWo + o] = wh;
                Cl[(long)(r + 8) * KWo + o] = wl;
            }
        }
    } else {
        // EPI == 2: transposed split planes, layout [B][EMB][SEQ/2 words].
        __syncthreads();               // everyone done reading stage buffers
        float* T = (float*)sm;
        const int TS = 130;
#pragma unroll
        for (int mi = 0; mi < 4; mi++) {
            const int r = wr * 64 + mi * 16 + gid;
#pragma unroll
            for (int ni = 0; ni < 8; ni++) {
                const int cc = wc * 64 + ni * 8 + 2 * tig;
                T[cc * TS + r]           = acc[mi][ni][0] * alpha;
                T[(cc + 1) * TS + r]     = acc[mi][ni][1] * alpha;
                T[cc * TS + r + 8]       = acc[mi][ni][2] * alpha;
                T[(cc + 1) * TS + r + 8] = acc[mi][ni][3] * alpha;
            }
        }
        __syncthreads();
        const int b  = rowBase / SEQ;
        const int n0 = rowBase - b * SEQ;
        const int cl = tid >> 6;        // 0..3
        const int rw = tid & 63;        // 0..63
#pragma unroll 4
        for (int cc = cl; cc < 256; cc += 4) {
            float x0 = T[cc * TS + 2 * rw];
            float x1 = T[cc * TS + 2 * rw + 1];
            uint32_t wh, wl;
            split_pair(x0, x1, wh, wl);
            const long o = ((long)b * EMB + colBase + cc) * (SEQ / 2) +
                           (n0 >> 1) + rw;
            Ch[o] = wh;
            Cl[o] = wl;
        }
    }
}

// ---------------------------------------------------------------------------
// Row softmax (in place on f32) + linear bf16 split side outputs.
// ---------------------------------------------------------------------------
__global__ void __launch_bounds__(256) softmax_rows(
    float* __restrict__ attn, uint32_t* __restrict__ hi,
    uint32_t* __restrict__ lo)
{
    const long row = blockIdx.x;
    float* p = attn + row * SEQ;
    uint32_t* hb = hi + row * (SEQ / 2);
    uint32_t* lb = lo + row * (SEQ / 2);
    const int tid  = threadIdx.x;
    const int lane = tid & 31;
    const int wid  = tid >> 5;
    __shared__ float red[8];

    float2 vals[4];
    float lmax = -INFINITY;
#pragma unroll
    for (int i = 0; i < 4; i++) {
        vals[i] = *(const float2*)(p + 2 * (tid + i * 256));
        lmax = fmaxf(lmax, fmaxf(vals[i].x, vals[i].y));
    }
#pragma unroll
    for (int o = 16; o > 0; o >>= 1)
        lmax = fmaxf(lmax, __shfl_xor_sync(0xFFFFFFFFu, lmax, o));
    if (lane == 0) red[wid] = lmax;
    __syncthreads();
    float m = red[0];
#pragma unroll
    for (int w = 1; w < 8; w++) m = fmaxf(m, red[w]);
    __syncthreads();   // protect red[] before reuse for the sum

    float lsum = 0.f;
#pragma unroll
    for (int i = 0; i < 4; i++) {
        vals[i].x = __expf(vals[i].x - m);
        vals[i].y = __expf(vals[i].y - m);
        lsum += vals[i].x + vals[i].y;
    }
#pragma unroll
    for (int o = 16; o > 0; o >>= 1)
        lsum += __shfl_xor_sync(0xFFFFFFFFu, lsum, o);
    if (lane == 0) red[wid] = lsum;
    __syncthreads();
    float tot = red[0];
#pragma unroll
    for (int w = 1; w < 8; w++) tot += red[w];

    const float inv = 1.f / tot;
#pragma unroll
    for (int i = 0; i < 4; i++) {
        const int w = tid + i * 256;
        float2 o2 = make_float2(vals[i].x * inv, vals[i].y * inv);
        *(float2*)(p + 2 * w) = o2;
        uint32_t wh, wl;
        split_pair(o2.x, o2.y, wh, wl);
        hb[w] = wh;
        lb[w] = wl;
    }
}

// ---------------------------------------------------------------------------
extern "C" void kernel_launch(void* const* d_in, const int* in_sizes, int n_in,
                              void* d_out, int out_size)
{
    const float* q  = (const float*)d_in[0];
    const float* k  = (const float*)d_in[1];
    const float* v  = (const float*)d_in[2];
    const float* Wq = (const float*)d_in[3];
    const float* Wk = (const float*)d_in[4];
    const float* Wv = (const float*)d_in[5];

    float* out  = (float*)d_out;                  // [B, N, E]
    float* attn = out + (long)BATCH * SEQ * EMB;  // [B, N, N]

    uint32_t *qh, *ql, *kh, *kl, *vh, *vl;
    uint32_t *Wqh, *Wql, *Wkh, *Wkl, *Wvh, *Wvl;
    uint32_t *qph, *qpl, *kph, *kpl, *vpth, *vptl, *ath, *atl;
    cudaGetSymbolAddress((void**)&qh,  g_qh);   cudaGetSymbolAddress((void**)&ql,  g_ql);
    cudaGetSymbolAddress((void**)&kh,  g_kh);   cudaGetSymbolAddress((void**)&kl,  g_kl);
    cudaGetSymbolAddress((void**)&vh,  g_vh);   cudaGetSymbolAddress((void**)&vl,  g_vl);
    cudaGetSymbolAddress((void**)&Wqh, g_Wqh);  cudaGetSymbolAddress((void**)&Wql, g_Wql);
    cudaGetSymbolAddress((void**)&Wkh, g_Wkh);  cudaGetSymbolAddress((void**)&Wkl, g_Wkl);
    cudaGetSymbolAddress((void**)&Wvh, g_Wvh);  cudaGetSymbolAddress((void**)&Wvl, g_Wvl);
    cudaGetSymbolAddress((void**)&qph, g_qph);  cudaGetSymbolAddress((void**)&qpl, g_qpl);
    cudaGetSymbolAddress((void**)&kph, g_kph);  cudaGetSymbolAddress((void**)&kpl, g_kpl);
    cudaGetSymbolAddress((void**)&vpth, g_vpth); cudaGetSymbolAddress((void**)&vptl, g_vptl);
    cudaGetSymbolAddress((void**)&ath, g_ath);  cudaGetSymbolAddress((void**)&atl, g_atl);

    cudaFuncSetAttribute(gemm_bs<0>, cudaFuncAttributeMaxDynamicSharedMemorySize, SMEM_BYTES);
    cudaFuncSetAttribute(gemm_bs<1>, cudaFuncAttributeMaxDynamicSharedMemorySize, SMEM_BYTES);
    cudaFuncSetAttribute(gemm_bs<2>, cudaFuncAttributeMaxDynamicSharedMemorySize, SMEM_BYTES);

    const float c = 0.044194173824159216f;  // 1/sqrt(512)

    // 1) split all inputs in one launch
    const long inWords = (long)BATCH * SEQ * DIM / 2;
    const long wWords  = (long)EMB * DIM / 2;
    const long totW = 3 * inWords + 3 * wWords;
    convert_all<<<(unsigned)((totW + 255) / 256), 256>>>(
        q, k, v, Wq, Wk, Wv,
        qh, ql, kh, kl, vh, vl,
        Wqh, Wql, Wkh, Wkl, Wvh, Wvl, inWords, wWords);

    // 2) projections  (M = B*N, N = EMB, K = DIM)
    dim3 gp(EMB / 256, (BATCH * SEQ) / 128, 1);
    gemm_bs<1><<<gp, 256, SMEM_BYTES>>>(qh, ql, Wqh, Wql, nullptr, qph, qpl,
                                        BATCH * SEQ, EMB, DIM, c, 0, 0, 0);
    gemm_bs<1><<<gp, 256, SMEM_BYTES>>>(kh, kl, Wkh, Wkl, nullptr, kph, kpl,
                                        BATCH * SEQ, EMB, DIM, c, 0, 0, 0);
    // v projection writes TRANSPOSED split planes directly (EPI=2)
    gemm_bs<2><<<gp, 256, SMEM_BYTES>>>(vh, vl, Wvh, Wvl, nullptr, vpth, vptl,
                                        BATCH * SEQ, EMB, DIM, c, 0, 0, 0);

    // 3) dots = qp @ kp^T * c -> attn (f32)
    dim3 gd(SEQ / 256, SEQ / 128, BATCH);
    gemm_bs<0><<<gd, 256, SMEM_BYTES>>>(qph, qpl, kph, kpl, attn, nullptr, nullptr,
                                        SEQ, SEQ, EMB, c,
                                        (long)SEQ * EMB / 2, (long)SEQ * EMB / 2,
                                        (long)SEQ * SEQ);

    // 4) softmax (f32 in place + split planes)
    softmax_rows<<<BATCH * SEQ, 256>>>(attn, ath, atl);

    // 5) out = attn @ vpt^T
    dim3 go(EMB / 256, SEQ / 128, BATCH);
    gemm_bs<0><<<go, 256, SMEM_BYTES>>>(ath, atl, vpth, vptl, out, nullptr, nullptr,
                                        SEQ, EMB, SEQ, 1.0f,
                                        (long)SEQ * SEQ / 2, (long)SEQ * EMB / 2,
                                        (long)SEQ * EMB);
}

// round 15
// speedup vs baseline: 1.8125x; 1.1797x over previous
#include <cuda_runtime.h>
#include <cuda_bf16.h>
#include <math.h>
#include <stdint.h>

#define BATCH 16
#define SEQ   2048
#define DIM   512
#define EMB   512

// ---------------------------------------------------------------------------
// Pre-split bf16 hi/lo planes (uint32 = 2 bf16), LINEAR k-order.
// ---------------------------------------------------------------------------
__device__ uint32_t g_qh [BATCH * SEQ * DIM / 2];
__device__ uint32_t g_ql [BATCH * SEQ * DIM / 2];
__device__ uint32_t g_kh [BATCH * SEQ * DIM / 2];
__device__ uint32_t g_kl [BATCH * SEQ * DIM / 2];
__device__ uint32_t g_vh [BATCH * SEQ * DIM / 2];
__device__ uint32_t g_vl [BATCH * SEQ * DIM / 2];
__device__ uint32_t g_Wqh[EMB * DIM / 2];
__device__ uint32_t g_Wql[EMB * DIM / 2];
__device__ uint32_t g_Wkh[EMB * DIM / 2];
__device__ uint32_t g_Wkl[EMB * DIM / 2];
__device__ uint32_t g_Wvh[EMB * DIM / 2];
__device__ uint32_t g_Wvl[EMB * DIM / 2];
__device__ uint32_t g_qph[BATCH * SEQ * EMB / 2];
__device__ uint32_t g_qpl[BATCH * SEQ * EMB / 2];
__device__ uint32_t g_kph[BATCH * SEQ * EMB / 2];
__device__ uint32_t g_kpl[BATCH * SEQ * EMB / 2];
__device__ uint32_t g_vpth[BATCH * EMB * SEQ / 2];
__device__ uint32_t g_vptl[BATCH * EMB * SEQ / 2];
__device__ uint32_t g_ath[(long)BATCH * SEQ * SEQ / 2];
__device__ uint32_t g_atl[(long)BATCH * SEQ * SEQ / 2];

// ---------------------------------------------------------------------------
// helpers
// ---------------------------------------------------------------------------
__device__ __forceinline__ uint32_t pack2bf(float e0, float e1) {
    uint32_t r;
    asm("cvt.rn.bf16x2.f32 %0, %1, %2;" : "=r"(r) : "f"(e1), "f"(e0));
    return r;
}

__device__ __forceinline__ void split_pair(float x0, float x1,
                                           uint32_t& wh, uint32_t& wl) {
    wh = pack2bf(x0, x1);
    float h0 = __uint_as_float(wh << 16);
    float h1 = __uint_as_float(wh & 0xFFFF0000u);
    wl = pack2bf(x0 - h0, x1 - h1);
}

__device__ __forceinline__ void mma_bf16(float* d, const uint32_t* a,
                                         const uint32_t* b) {
    asm volatile(
        "mma.sync.aligned.m16n8k16.row.col.f32.bf16.bf16.f32 "
        "{%0,%1,%2,%3},{%4,%5,%6,%7},{%8,%9},{%0,%1,%2,%3};"
        : "+f"(d[0]), "+f"(d[1]), "+f"(d[2]), "+f"(d[3])
        : "r"(a[0]), "r"(a[1]), "r"(a[2]), "r"(a[3]), "r"(b[0]), "r"(b[1]));
}

__device__ __forceinline__ uint32_t smem_u32(const void* p) {
    uint32_t a;
    asm("{ .reg .u64 t; cvta.to.shared.u64 t, %1; cvt.u32.u64 %0, t; }"
        : "=r"(a) : "l"(p));
    return a;
}

#define LDSM4(r0, r1, r2, r3, a) \
    asm volatile("ldmatrix.sync.aligned.m8n8.x4.shared.b16 {%0,%1,%2,%3}, [%4];" \
                 : "=r"(r0), "=r"(r1), "=r"(r2), "=r"(r3) : "r"(a))

#define CP16(dst, src) \
    asm volatile("cp.async.cg.shared.global [%0], [%1], 16;" \
                 :: "r"(dst), "l"(src) : "memory")
#define CP_COMMIT() asm volatile("cp.async.commit_group;" ::: "memory")
#define CP_WAIT1()  asm volatile("cp.async.wait_group 1;"  ::: "memory")

// ---------------------------------------------------------------------------
// one-shot conversion of all six inputs -> hi/lo bf16 planes (linear)
// ---------------------------------------------------------------------------
__global__ void __launch_bounds__(256) convert_all(
    const float* __restrict__ q, const float* __restrict__ k,
    const float* __restrict__ v, const float* __restrict__ Wq,
    const float* __restrict__ Wk, const float* __restrict__ Wv,
    uint32_t* __restrict__ qh, uint32_t* __restrict__ ql,
    uint32_t* __restrict__ kh, uint32_t* __restrict__ kl,
    uint32_t* __restrict__ vh, uint32_t* __restrict__ vl,
    uint32_t* __restrict__ Wqh, uint32_t* __restrict__ Wql,
    uint32_t* __restrict__ Wkh, uint32_t* __restrict__ Wkl,
    uint32_t* __restrict__ Wvh, uint32_t* __restrict__ Wvl,
    long inWords, long wWords)
{
    long w = (long)blockIdx.x * 256 + threadIdx.x;
    const float* src;
    uint32_t *hi, *lo;
    long idx;
    if (w < 3 * inWords) {
        int sel = (int)(w / inWords);
        idx = w - (long)sel * inWords;
        src = sel == 0 ? q : sel == 1 ? k : v;
        hi  = sel == 0 ? qh : sel == 1 ? kh : vh;
        lo  = sel == 0 ? ql : sel == 1 ? kl : vl;
    } else {
        long w2 = w - 3 * inWords;
        if (w2 >= 3 * wWords) return;
        int sel = (int)(w2 / wWords);
        idx = w2 - (long)sel * wWords;
        src = sel == 0 ? Wq : sel == 1 ? Wk : Wv;
        hi  = sel == 0 ? Wqh : sel == 1 ? Wkh : Wvh;
        lo  = sel == 0 ? Wql : sel == 1 ? Wkl : Wvl;
    }
    float2 val = *(const float2*)(src + 2 * idx);
    uint32_t wh2, wl2;
    split_pair(val.x, val.y, wh2, wl2);
    hi[idx] = wh2;
    lo[idx] = wl2;
}

// ---------------------------------------------------------------------------
// GEMM: C = alpha * A @ B^T on pre-split planes (3-mma bf16 split: hh,hl,lh).
// CTA tile 128(M) x 128(N), BK=32, 8 warps (2x4), 64x32 warp tiles,
// cp.async DOUBLE-buffered, ldmatrix fragment loads.
// RACE-FREE double buffer: stage s+2 (same buffer as s) is issued only AFTER
// the bottom __syncthreads() of stage s's compute. Stage s+1 stays in flight
// during compute of s (the overlap). Unconditional commit keeps wait_group
// accounting identical to the proven 3-stage variant.
// __launch_bounds__(256, 2) -> 2 CTAs/SM (4 warps/SMSP) for latency hiding.
// EPI 0: f32 C.  EPI 1: linear split planes Ch/Cl.
// EPI 2: TRANSPOSED split planes (vpt layout [B][EMB][SEQ/2]), smem-staged.
// ---------------------------------------------------------------------------
#define SROW     20
#define A_PL     (128 * SROW)            // 2560 words
#define B_PL     (128 * SROW)            // 2560 words
#define STAGE_W  (2 * A_PL + 2 * B_PL)   // 10240 words = 40960 B
#define SMEM_BYTES (2 * STAGE_W * 4)     // 81920 B  (>= 128*130*4 for EPI=2)

template <int EPI>
__global__ void __launch_bounds__(256, 2) gemm_bs(
    const uint32_t* __restrict__ Ah, const uint32_t* __restrict__ Al,
    const uint32_t* __restrict__ Bh, const uint32_t* __restrict__ Bl,
    float* __restrict__ C, uint32_t* __restrict__ Ch, uint32_t* __restrict__ Cl,
    int M, int Nn, int K, float alpha, long sA, long sB, long sC)
{
    extern __shared__ uint32_t sm[];

    const int tid  = threadIdx.x;
    const int lane = tid & 31;
    const int warp = tid >> 5;
    const int gid  = lane >> 2;
    const int tig  = lane & 3;
    const int wr   = warp & 1;     // 2 warp-rows (64 rows each)
    const int wc   = warp >> 1;    // 4 warp-cols (32 cols each)
    const int lm8  = lane & 7;     // ldmatrix: row within 8x8 tile
    const int ts   = lane >> 3;    // ldmatrix: tile selector 0..3

    const int KW = K >> 1;
    Ah += (long)blockIdx.z * sA;  Al += (long)blockIdx.z * sA;
    Bh += (long)blockIdx.z * sB;  Bl += (long)blockIdx.z * sB;
    C  += (long)blockIdx.z * sC;
    const int rowBase = blockIdx.y * 128;
    const int colBase = blockIdx.x * 128;

    // cp.async loaders (linear k copy)
    const int lrow = tid >> 1;            // 0..127
    const int kh   = tid & 1;             // 8-word half
    const uint32_t* gAh = Ah + (long)(rowBase + lrow) * KW + 8 * kh;
    const uint32_t* gAl = Al + (long)(rowBase + lrow) * KW + 8 * kh;
    const uint32_t* gBh = Bh + (long)(colBase + lrow) * KW + 8 * kh;
    const uint32_t* gBl = Bl + (long)(colBase + lrow) * KW + 8 * kh;

    const int sp = lrow * SROW + 8 * kh;

    const uint32_t smb = smem_u32(sm);

    auto issue_stage = [&](int s) {
        const uint32_t bb = smb + ((s & 1) * STAGE_W) * 4;
        const long o = (long)s * 16;
        CP16(bb + sp * 4,                           gAh + o);
        CP16(bb + (sp + 4) * 4,                     gAh + o + 4);
        CP16(bb + (A_PL + sp) * 4,                  gAl + o);
        CP16(bb + (A_PL + sp + 4) * 4,              gAl + o + 4);
        CP16(bb + (2 * A_PL + sp) * 4,              gBh + o);
        CP16(bb + (2 * A_PL + sp + 4) * 4,          gBh + o + 4);
        CP16(bb + (2 * A_PL + B_PL + sp) * 4,       gBl + o);
        CP16(bb + (2 * A_PL + B_PL + sp + 4) * 4,   gBl + o + 4);
    };

    // ldmatrix per-lane base byte-offsets (within a stage)
    uint32_t aBase[4];
#pragma unroll
    for (int mi = 0; mi < 4; mi++)
        aBase[mi] = ((wr * 64 + mi * 16 + ((ts & 1) << 3) + lm8) * SROW +
                     (ts >> 1) * 4) * 4;
    uint32_t bBase[2];
#pragma unroll
    for (int p = 0; p < 2; p++)
        bBase[p] = ((wc * 32 + p * 16 + ((ts >> 1) << 3) + lm8) * SROW +
                    (ts & 1) * 4) * 4;

    float acc[4][4][4];
#pragma unroll
    for (int i = 0; i < 4; i++)
#pragma unroll
        for (int j = 0; j < 4; j++)
#pragma unroll
            for (int r = 0; r < 4; r++) acc[i][j][r] = 0.f;

    const int NS = K / 32;
    issue_stage(0); CP_COMMIT();
    issue_stage(1); CP_COMMIT();

    for (int s = 0; s < NS; s++) {
        CP_WAIT1();        // stage s's group (and all before) complete
        __syncthreads();

        const uint32_t stb = smb + (s & 1) * STAGE_W * 4;

#pragma unroll
        for (int kk = 0; kk < 2; kk++) {
            uint32_t af[4][2][4];
#pragma unroll
            for (int mi = 0; mi < 4; mi++)
#pragma unroll
                for (int h = 0; h < 2; h++) {
                    const uint32_t ad = stb + h * (A_PL * 4) + aBase[mi] + kk * 32;
                    LDSM4(af[mi][h][0], af[mi][h][1], af[mi][h][2], af[mi][h][3], ad);
                }
#pragma unroll
            for (int p = 0; p < 2; p++) {
                const uint32_t bhA = stb + (2 * A_PL) * 4 + bBase[p] + kk * 32;
                uint32_t bh[4], bl[4];
                LDSM4(bh[0], bh[1], bh[2], bh[3], bhA);
                LDSM4(bl[0], bl[1], bl[2], bl[3], bhA + B_PL * 4);
#pragma unroll
                for (int mi = 0; mi < 4; mi++) {
                    mma_bf16(acc[mi][2 * p],     af[mi][0], bh);      // hh
                    mma_bf16(acc[mi][2 * p],     af[mi][0], bl);      // hl
                    mma_bf16(acc[mi][2 * p],     af[mi][1], bh);      // lh
                    mma_bf16(acc[mi][2 * p + 1], af[mi][0], bh + 2);
                    mma_bf16(acc[mi][2 * p + 1], af[mi][0], bl + 2);
                    mma_bf16(acc[mi][2 * p + 1], af[mi][1], bh + 2);
                }
            }
        }

        __syncthreads();   // all warps done READING buffer s&1
        if (s + 2 < NS) issue_stage(s + 2);   // safe: writes buffer s&1
        CP_COMMIT();       // unconditional: keeps group accounting aligned
    }

    if (EPI == 0) {
#pragma unroll
        for (int mi = 0; mi < 4; mi++) {
            const int r = rowBase + wr * 64 + mi * 16 + gid;
#pragma unroll
            for (int ni = 0; ni < 4; ni++) {
                const int cc = colBase + wc * 32 + ni * 8 + 2 * tig;
                float2 v0 = make_float2(acc[mi][ni][0] * alpha, acc[mi][ni][1] * alpha);
                float2 v1 = make_float2(acc[mi][ni][2] * alpha, acc[mi][ni][3] * alpha);
                *(float2*)(C + (long)r * Nn + cc)       = v0;
                *(float2*)(C + (long)(r + 8) * Nn + cc) = v1;
            }
        }
    } else if (EPI == 1) {
        // linear split-plane outputs (z-grid must be 1)
        const int KWo = Nn >> 1;
#pragma unroll
        for (int mi = 0; mi < 4; mi++) {
            const int r = rowBase + wr * 64 + mi * 16 + gid;
#pragma unroll
            for (int ni = 0; ni < 4; ni++) {
                const long o = (long)(colBase >> 1) + wc * 16 + ni * 4 + tig;
                uint32_t wh, wl;
                split_pair(acc[mi][ni][0] * alpha, acc[mi][ni][1] * alpha, wh, wl);
                Ch[(long)r * KWo + o] = wh;
                Cl[(long)r * KWo + o] = wl;
                split_pair(acc[mi][ni][2] * alpha, acc[mi][ni][3] * alpha, wh, wl);
                Ch[(long)(r + 8) * KWo + o] = wh;
                Cl[(long)(r + 8) * KWo + o] = wl;
            }
        }
    } else {
        // EPI == 2: transposed split planes, layout [B][EMB][SEQ/2 words].
        // (last loop iteration ended with __syncthreads; stage buffers free)
        float* T = (float*)sm;
        const int TS = 130;            // 128x130 f32 = 66560 B < SMEM_BYTES
#pragma unroll
        for (int mi = 0; mi < 4; mi++) {
            const int r = wr * 64 + mi * 16 + gid;
#pragma unroll
            for (int ni = 0; ni < 4; ni++) {
                const int cc = wc * 32 + ni * 8 + 2 * tig;
                T[cc * TS + r]           = acc[mi][ni][0] * alpha;
                T[(cc + 1) * TS + r]     = acc[mi][ni][1] * alpha;
                T[cc * TS + r + 8]       = acc[mi][ni][2] * alpha;
                T[(cc + 1) * TS + r + 8] = acc[mi][ni][3] * alpha;
            }
        }
        __syncthreads();
        const int b  = rowBase / SEQ;
        const int n0 = rowBase - b * SEQ;
        const int cl = tid >> 6;        // 0..3
        const int rw = tid & 63;        // 0..63
#pragma unroll 4
        for (int cc = cl; cc < 128; cc += 4) {
            float x0 = T[cc * TS + 2 * rw];
            float x1 = T[cc * TS + 2 * rw + 1];
            uint32_t wh, wl;
            split_pair(x0, x1, wh, wl);
            const long o = ((long)b * EMB + colBase + cc) * (SEQ / 2) +
                           (n0 >> 1) + rw;
            Ch[o] = wh;
            Cl[o] = wl;
        }
    }
}

// ---------------------------------------------------------------------------
// Row softmax (in place on f32) + linear bf16 split side outputs.
// ---------------------------------------------------------------------------
__global__ void __launch_bounds__(256) softmax_rows(
    float* __restrict__ attn, uint32_t* __restrict__ hi,
    uint32_t* __restrict__ lo)
{
    const long row = blockIdx.x;
    float* p = attn + row * SEQ;
    uint32_t* hb = hi + row * (SEQ / 2);
    uint32_t* lb = lo + row * (SEQ / 2);
    const int tid  = threadIdx.x;
    const int lane = tid & 31;
    const int wid  = tid >> 5;
    __shared__ float red[8];

    float2 vals[4];
    float lmax = -INFINITY;
#pragma unroll
    for (int i = 0; i < 4; i++) {
        vals[i] = *(const float2*)(p + 2 * (tid + i * 256));
        lmax = fmaxf(lmax, fmaxf(vals[i].x, vals[i].y));
    }
#pragma unroll
    for (int o = 16; o > 0; o >>= 1)
        lmax = fmaxf(lmax, __shfl_xor_sync(0xFFFFFFFFu, lmax, o));
    if (lane == 0) red[wid] = lmax;
    __syncthreads();
    float m = red[0];
#pragma unroll
    for (int w = 1; w < 8; w++) m = fmaxf(m, red[w]);
    __syncthreads();   // protect red[] before reuse for the sum

    float lsum = 0.f;
#pragma unroll
    for (int i = 0; i < 4; i++) {
        vals[i].x = __expf(vals[i].x - m);
        vals[i].y = __expf(vals[i].y - m);
        lsum += vals[i].x + vals[i].y;
    }
#pragma unroll
    for (int o = 16; o > 0; o >>= 1)
        lsum += __shfl_xor_sync(0xFFFFFFFFu, lsum, o);
    if (lane == 0) red[wid] = lsum;
    __syncthreads();
    float tot = red[0];
#pragma unroll
    for (int w = 1; w < 8; w++) tot += red[w];

    const float inv = 1.f / tot;
#pragma unroll
    for (int i = 0; i < 4; i++) {
        const int w = tid + i * 256;
        float2 o2 = make_float2(vals[i].x * inv, vals[i].y * inv);
        *(float2*)(p + 2 * w) = o2;
        uint32_t wh, wl;
        split_pair(o2.x, o2.y, wh, wl);
        hb[w] = wh;
        lb[w] = wl;
    }
}

// ---------------------------------------------------------------------------
extern "C" void kernel_launch(void* const* d_in, const int* in_sizes, int n_in,
                              void* d_out, int out_size)
{
    const float* q  = (const float*)d_in[0];
    const float* k  = (const float*)d_in[1];
    const float* v  = (const float*)d_in[2];
    const float* Wq = (const float*)d_in[3];
    const float* Wk = (const float*)d_in[4];
    const float* Wv = (const float*)d_in[5];

    float* out  = (float*)d_out;                  // [B, N, E]
    float* attn = out + (long)BATCH * SEQ * EMB;  // [B, N, N]

    uint32_t *qh, *ql, *kh, *kl, *vh, *vl;
    uint32_t *Wqh, *Wql, *Wkh, *Wkl, *Wvh, *Wvl;
    uint32_t *qph, *qpl, *kph, *kpl, *vpth, *vptl, *ath, *atl;
    cudaGetSymbolAddress((void**)&qh,  g_qh);   cudaGetSymbolAddress((void**)&ql,  g_ql);
    cudaGetSymbolAddress((void**)&kh,  g_kh);   cudaGetSymbolAddress((void**)&kl,  g_kl);
    cudaGetSymbolAddress((void**)&vh,  g_vh);   cudaGetSymbolAddress((void**)&vl,  g_vl);
    cudaGetSymbolAddress((void**)&Wqh, g_Wqh);  cudaGetSymbolAddress((void**)&Wql, g_Wql);
    cudaGetSymbolAddress((void**)&Wkh, g_Wkh);  cudaGetSymbolAddress((void**)&Wkl, g_Wkl);
    cudaGetSymbolAddress((void**)&Wvh, g_Wvh);  cudaGetSymbolAddress((void**)&Wvl, g_Wvl);
    cudaGetSymbolAddress((void**)&qph, g_qph);  cudaGetSymbolAddress((void**)&qpl, g_qpl);
    cudaGetSymbolAddress((void**)&kph, g_kph);  cudaGetSymbolAddress((void**)&kpl, g_kpl);
    cudaGetSymbolAddress((void**)&vpth, g_vpth); cudaGetSymbolAddress((void**)&vptl, g_vptl);
    cudaGetSymbolAddress((void**)&ath, g_ath);  cudaGetSymbolAddress((void**)&atl, g_atl);

    cudaFuncSetAttribute(gemm_bs<0>, cudaFuncAttributeMaxDynamicSharedMemorySize, SMEM_BYTES);
    cudaFuncSetAttribute(gemm_bs<1>, cudaFuncAttributeMaxDynamicSharedMemorySize, SMEM_BYTES);
    cudaFuncSetAttribute(gemm_bs<2>, cudaFuncAttributeMaxDynamicSharedMemorySize, SMEM_BYTES);

    const float c = 0.044194173824159216f;  // 1/sqrt(512)

    // 1) split all inputs in one launch
    const long inWords = (long)BATCH * SEQ * DIM / 2;
    const long wWords  = (long)EMB * DIM / 2;
    const long totW = 3 * inWords + 3 * wWords;
    convert_all<<<(unsigned)((totW + 255) / 256), 256>>>(
        q, k, v, Wq, Wk, Wv,
        qh, ql, kh, kl, vh, vl,
        Wqh, Wql, Wkh, Wkl, Wvh, Wvl, inWords, wWords);

    // 2) projections  (M = B*N, N = EMB, K = DIM)
    dim3 gp(EMB / 128, (BATCH * SEQ) / 128, 1);
    gemm_bs<1><<<gp, 256, SMEM_BYTES>>>(qh, ql, Wqh, Wql, nullptr, qph, qpl,
                                        BATCH * SEQ, EMB, DIM, c, 0, 0, 0);
    gemm_bs<1><<<gp, 256, SMEM_BYTES>>>(kh, kl, Wkh, Wkl, nullptr, kph, kpl,
                                        BATCH * SEQ, EMB, DIM, c, 0, 0, 0);
    // v projection writes TRANSPOSED split planes directly (EPI=2)
    gemm_bs<2><<<gp, 256, SMEM_BYTES>>>(vh, vl, Wvh, Wvl, nullptr, vpth, vptl,
                                        BATCH * SEQ, EMB, DIM, c, 0, 0, 0);

    // 3) dots = qp @ kp^T * c -> attn (f32)
    dim3 gd(SEQ / 128, SEQ / 128, BATCH);
    gemm_bs<0><<<gd, 256, SMEM_BYTES>>>(qph, qpl, kph, kpl, attn, nullptr, nullptr,
                                        SEQ, SEQ, EMB, c,
                                        (long)SEQ * EMB / 2, (long)SEQ * EMB / 2,
                                        (long)SEQ * SEQ);

    // 4) softmax (f32 in place + split planes)
    softmax_rows<<<BATCH * SEQ, 256>>>(attn, ath, atl);

    // 5) out = attn @ vpt^T
    dim3 go(EMB / 128, SEQ / 128, BATCH);
    gemm_bs<0><<<go, 256, SMEM_BYTES>>>(ath, atl, vpth, vptl, out, nullptr, nullptr,
                                        SEQ, EMB, SEQ, 1.0f,
                                        (long)SEQ * SEQ / 2, (long)SEQ * EMB / 2,
                                        (long)SEQ * EMB);
}

// round 16
// speedup vs baseline: 1.8559x; 1.0240x over previous
#include <cuda_runtime.h>
#include <cuda_bf16.h>
#include <math.h>
#include <stdint.h>

#define BATCH 16
#define SEQ   2048
#define DIM   512
#define EMB   512

// ---------------------------------------------------------------------------
// Pre-split bf16 hi/lo planes (uint32 = 2 bf16), LINEAR k-order.
// ---------------------------------------------------------------------------
__device__ uint32_t g_qh [BATCH * SEQ * DIM / 2];
__device__ uint32_t g_ql [BATCH * SEQ * DIM / 2];
__device__ uint32_t g_kh [BATCH * SEQ * DIM / 2];
__device__ uint32_t g_kl [BATCH * SEQ * DIM / 2];
__device__ uint32_t g_vh [BATCH * SEQ * DIM / 2];
__device__ uint32_t g_vl [BATCH * SEQ * DIM / 2];
__device__ uint32_t g_Wqh[EMB * DIM / 2];
__device__ uint32_t g_Wql[EMB * DIM / 2];
__device__ uint32_t g_Wkh[EMB * DIM / 2];
__device__ uint32_t g_Wkl[EMB * DIM / 2];
__device__ uint32_t g_Wvh[EMB * DIM / 2];
__device__ uint32_t g_Wvl[EMB * DIM / 2];
__device__ uint32_t g_qph[BATCH * SEQ * EMB / 2];
__device__ uint32_t g_qpl[BATCH * SEQ * EMB / 2];
__device__ uint32_t g_kph[BATCH * SEQ * EMB / 2];
__device__ uint32_t g_kpl[BATCH * SEQ * EMB / 2];
__device__ uint32_t g_vpth[BATCH * EMB * SEQ / 2];
__device__ uint32_t g_vptl[BATCH * EMB * SEQ / 2];
__device__ uint32_t g_ath[(long)BATCH * SEQ * SEQ / 2];
__device__ uint32_t g_atl[(long)BATCH * SEQ * SEQ / 2];

// ---------------------------------------------------------------------------
// helpers
// ---------------------------------------------------------------------------
__device__ __forceinline__ uint32_t pack2bf(float e0, float e1) {
    uint32_t r;
    asm("cvt.rn.bf16x2.f32 %0, %1, %2;" : "=r"(r) : "f"(e1), "f"(e0));
    return r;
}

__device__ __forceinline__ void split_pair(float x0, float x1,
                                           uint32_t& wh, uint32_t& wl) {
    wh = pack2bf(x0, x1);
    float h0 = __uint_as_float(wh << 16);
    float h1 = __uint_as_float(wh & 0xFFFF0000u);
    wl = pack2bf(x0 - h0, x1 - h1);
}

__device__ __forceinline__ void mma_bf16(float* d, const uint32_t* a,
                                         const uint32_t* b) {
    asm volatile(
        "mma.sync.aligned.m16n8k16.row.col.f32.bf16.bf16.f32 "
        "{%0,%1,%2,%3},{%4,%5,%6,%7},{%8,%9},{%0,%1,%2,%3};"
        : "+f"(d[0]), "+f"(d[1]), "+f"(d[2]), "+f"(d[3])
        : "r"(a[0]), "r"(a[1]), "r"(a[2]), "r"(a[3]), "r"(b[0]), "r"(b[1]));
}

__device__ __forceinline__ uint32_t smem_u32(const void* p) {
    uint32_t a;
    asm("{ .reg .u64 t; cvta.to.shared.u64 t, %1; cvt.u32.u64 %0, t; }"
        : "=r"(a) : "l"(p));
    return a;
}

#define LDSM4(r0, r1, r2, r3, a) \
    asm volatile("ldmatrix.sync.aligned.m8n8.x4.shared.b16 {%0,%1,%2,%3}, [%4];" \
                 : "=r"(r0), "=r"(r1), "=r"(r2), "=r"(r3) : "r"(a))

#define CP16(dst, src) \
    asm volatile("cp.async.cg.shared.global [%0], [%1], 16;" \
                 :: "r"(dst), "l"(src) : "memory")
#define CP_COMMIT() asm volatile("cp.async.commit_group;" ::: "memory")
#define CP_WAIT1()  asm volatile("cp.async.wait_group 1;"  ::: "memory")

// ---------------------------------------------------------------------------
// one-shot conversion of all six inputs -> hi/lo bf16 planes (linear)
// ---------------------------------------------------------------------------
__global__ void __launch_bounds__(256) convert_all(
    const float* __restrict__ q, const float* __restrict__ k,
    const float* __restrict__ v, const float* __restrict__ Wq,
    const float* __restrict__ Wk, const float* __restrict__ Wv,
    uint32_t* __restrict__ qh, uint32_t* __restrict__ ql,
    uint32_t* __restrict__ kh, uint32_t* __restrict__ kl,
    uint32_t* __restrict__ vh, uint32_t* __restrict__ vl,
    uint32_t* __restrict__ Wqh, uint32_t* __restrict__ Wql,
    uint32_t* __restrict__ Wkh, uint32_t* __restrict__ Wkl,
    uint32_t* __restrict__ Wvh, uint32_t* __restrict__ Wvl,
    long inWords, long wWords)
{
    long w = (long)blockIdx.x * 256 + threadIdx.x;
    const float* src;
    uint32_t *hi, *lo;
    long idx;
    if (w < 3 * inWords) {
        int sel = (int)(w / inWords);
        idx = w - (long)sel * inWords;
        src = sel == 0 ? q : sel == 1 ? k : v;
        hi  = sel == 0 ? qh : sel == 1 ? kh : vh;
        lo  = sel == 0 ? ql : sel == 1 ? kl : vl;
    } else {
        long w2 = w - 3 * inWords;
        if (w2 >= 3 * wWords) return;
        int sel = (int)(w2 / wWords);
        idx = w2 - (long)sel * wWords;
        src = sel == 0 ? Wq : sel == 1 ? Wk : Wv;
        hi  = sel == 0 ? Wqh : sel == 1 ? Wkh : Wvh;
        lo  = sel == 0 ? Wql : sel == 1 ? Wkl : Wvl;
    }
    float2 val = *(const float2*)(src + 2 * idx);
    uint32_t wh2, wl2;
    split_pair(val.x, val.y, wh2, wl2);
    hi[idx] = wh2;
    lo[idx] = wl2;
}

// ---------------------------------------------------------------------------
// GEMM: C = alpha * A @ B^T on pre-split planes (3-mma bf16 split: hh,hl,lh).
// CTA tile 128(M) x 128(N), BK=32, 8 warps (2x4), 64x32 warp tiles.
// 3-STAGE cp.async ring (1 sync/stage, 2 stages in flight) with XOR-swizzled
// smem (16-word rows, chunk c of row r stored at c ^ ((r>>1)&3)) -> 32 KB
// stages, 96 KB total, 2 CTAs/SM kept via __launch_bounds__(256, 2).
// EPI 0: f32 C.  EPI 1: linear split planes Ch/Cl.
// EPI 2: TRANSPOSED split planes (vpt layout [B][EMB][SEQ/2]), smem-staged.
// ---------------------------------------------------------------------------
#define A_PL     (128 * 16)              // 2048 words per plane
#define B_PL     (128 * 16)
#define STAGE_W  (4 * 2048)              // 8192 words = 32768 B
#define SMEM_BYTES (3 * STAGE_W * 4)     // 98304 B  (>= 128*130*4 for EPI=2)

template <int EPI>
__global__ void __launch_bounds__(256, 2) gemm_bs(
    const uint32_t* __restrict__ Ah, const uint32_t* __restrict__ Al,
    const uint32_t* __restrict__ Bh, const uint32_t* __restrict__ Bl,
    float* __restrict__ C, uint32_t* __restrict__ Ch, uint32_t* __restrict__ Cl,
    int M, int Nn, int K, float alpha, long sA, long sB, long sC)
{
    extern __shared__ uint32_t sm[];

    const int tid  = threadIdx.x;
    const int lane = tid & 31;
    const int warp = tid >> 5;
    const int gid  = lane >> 2;
    const int tig  = lane & 3;
    const int wr   = warp & 1;     // 2 warp-rows (64 rows each)
    const int wc   = warp >> 1;    // 4 warp-cols (32 cols each)
    const int lm8  = lane & 7;     // ldmatrix: row within 8x8 tile
    const int ts   = lane >> 3;    // ldmatrix: tile selector 0..3

    const int KW = K >> 1;
    Ah += (long)blockIdx.z * sA;  Al += (long)blockIdx.z * sA;
    Bh += (long)blockIdx.z * sB;  Bl += (long)blockIdx.z * sB;
    C  += (long)blockIdx.z * sC;
    const int rowBase = blockIdx.y * 128;
    const int colBase = blockIdx.x * 128;

    // cp.async loaders (linear k copy, swizzled dst)
    const int lrow = tid >> 1;            // 0..127
    const int kh   = tid & 1;             // 8-word half
    const uint32_t* gAh = Ah + (long)(rowBase + lrow) * KW + 8 * kh;
    const uint32_t* gAl = Al + (long)(rowBase + lrow) * KW + 8 * kh;
    const uint32_t* gBh = Bh + (long)(colBase + lrow) * KW + 8 * kh;
    const uint32_t* gBl = Bl + (long)(colBase + lrow) * KW + 8 * kh;

    const int rx = (lrow >> 1) & 3;
    const uint32_t d0 = lrow * 64 + ((uint32_t)((2 * kh)     ^ rx) << 4);
    const uint32_t d1 = lrow * 64 + ((uint32_t)((2 * kh + 1) ^ rx) << 4);

    const uint32_t smb = smem_u32(sm);

    auto issue_stage = [&](int s) {
        const uint32_t bb = smb + ((s % 3) * STAGE_W) * 4;
        const long o = (long)s * 16;
        CP16(bb + d0,                        gAh + o);
        CP16(bb + d1,                        gAh + o + 4);
        CP16(bb + A_PL * 4 + d0,             gAl + o);
        CP16(bb + A_PL * 4 + d1,             gAl + o + 4);
        CP16(bb + 2 * A_PL * 4 + d0,         gBh + o);
        CP16(bb + 2 * A_PL * 4 + d1,         gBh + o + 4);
        CP16(bb + (2 * A_PL + B_PL) * 4 + d0, gBl + o);
        CP16(bb + (2 * A_PL + B_PL) * 4 + d1, gBl + o + 4);
    };

    // ldmatrix per-lane row byte-offsets + swizzle keys
    uint32_t aOff[4]; int aRx[4];
#pragma unroll
    for (int mi = 0; mi < 4; mi++) {
        const int r = wr * 64 + mi * 16 + ((ts & 1) << 3) + lm8;
        aOff[mi] = r * 64;
        aRx[mi]  = (r >> 1) & 3;
    }
    uint32_t bOff[2]; int bRx[2];
#pragma unroll
    for (int p = 0; p < 2; p++) {
        const int r = wc * 32 + p * 16 + ((ts >> 1) << 3) + lm8;
        bOff[p] = r * 64;
        bRx[p]  = (r >> 1) & 3;
    }

    float acc[4][4][4];
#pragma unroll
    for (int i = 0; i < 4; i++)
#pragma unroll
        for (int j = 0; j < 4; j++)
#pragma unroll
            for (int r = 0; r < 4; r++) acc[i][j][r] = 0.f;

    const int NS = K / 32;
    issue_stage(0); CP_COMMIT();
    issue_stage(1); CP_COMMIT();

    for (int s = 0; s < NS; s++) {
        CP_WAIT1();
        __syncthreads();   // stage s ready; all warps done with stage s-1

        if (s + 2 < NS) issue_stage(s + 2);   // buffer (s+2)%3 == (s-1)%3: free
        CP_COMMIT();

        const uint32_t stb = smb + (s % 3) * STAGE_W * 4;

#pragma unroll
        for (int kk = 0; kk < 2; kk++) {
            uint32_t af[4][2][4];
            const int kcA = (ts >> 1) + 2 * kk;
#pragma unroll
            for (int mi = 0; mi < 4; mi++)
#pragma unroll
                for (int h = 0; h < 2; h++) {
                    const uint32_t ad = stb + h * (A_PL * 4) + aOff[mi] +
                                        ((uint32_t)(kcA ^ aRx[mi]) << 4);
                    LDSM4(af[mi][h][0], af[mi][h][1], af[mi][h][2], af[mi][h][3], ad);
                }
            const int kcB = (ts & 1) + 2 * kk;
#pragma unroll
            for (int p = 0; p < 2; p++) {
                const uint32_t bA = stb + 2 * A_PL * 4 + bOff[p] +
                                    ((uint32_t)(kcB ^ bRx[p]) << 4);
                uint32_t bh[4], bl[4];
                LDSM4(bh[0], bh[1], bh[2], bh[3], bA);
                LDSM4(bl[0], bl[1], bl[2], bl[3], bA + B_PL * 4);
#pragma unroll
                for (int mi = 0; mi < 4; mi++) {
                    mma_bf16(acc[mi][2 * p],     af[mi][0], bh);      // hh
                    mma_bf16(acc[mi][2 * p],     af[mi][0], bl);      // hl
                    mma_bf16(acc[mi][2 * p],     af[mi][1], bh);      // lh
                    mma_bf16(acc[mi][2 * p + 1], af[mi][0], bh + 2);
                    mma_bf16(acc[mi][2 * p + 1], af[mi][0], bl + 2);
                    mma_bf16(acc[mi][2 * p + 1], af[mi][1], bh + 2);
                }
            }
        }
    }

    if (EPI == 0) {
#pragma unroll
        for (int mi = 0; mi < 4; mi++) {
            const int r = rowBase + wr * 64 + mi * 16 + gid;
#pragma unroll
            for (int ni = 0; ni < 4; ni++) {
                const int cc = colBase + wc * 32 + ni * 8 + 2 * tig;
                float2 v0 = make_float2(acc[mi][ni][0] * alpha, acc[mi][ni][1] * alpha);
                float2 v1 = make_float2(acc[mi][ni][2] * alpha, acc[mi][ni][3] * alpha);
                *(float2*)(C + (long)r * Nn + cc)       = v0;
                *(float2*)(C + (long)(r + 8) * Nn + cc) = v1;
            }
        }
    } else if (EPI == 1) {
        // linear split-plane outputs (z-grid must be 1)
        const int KWo = Nn >> 1;
#pragma unroll
        for (int mi = 0; mi < 4; mi++) {
            const int r = rowBase + wr * 64 + mi * 16 + gid;
#pragma unroll
            for (int ni = 0; ni < 4; ni++) {
                const long o = (long)(colBase >> 1) + wc * 16 + ni * 4 + tig;
                uint32_t wh, wl;
                split_pair(acc[mi][ni][0] * alpha, acc[mi][ni][1] * alpha, wh, wl);
                Ch[(long)r * KWo + o] = wh;
                Cl[(long)r * KWo + o] = wl;
                split_pair(acc[mi][ni][2] * alpha, acc[mi][ni][3] * alpha, wh, wl);
                Ch[(long)(r + 8) * KWo + o] = wh;
                Cl[(long)(r + 8) * KWo + o] = wl;
            }
        }
    } else {
        // EPI == 2: transposed split planes, layout [B][EMB][SEQ/2 words].
        __syncthreads();               // everyone done reading stage buffers
        float* T = (float*)sm;
        const int TS = 130;            // 128x130 f32 = 66560 B < SMEM_BYTES
#pragma unroll
        for (int mi = 0; mi < 4; mi++) {
            const int r = wr * 64 + mi * 16 + gid;
#pragma unroll
            for (int ni = 0; ni < 4; ni++) {
                const int cc = wc * 32 + ni * 8 + 2 * tig;
                T[cc * TS + r]           = acc[mi][ni][0] * alpha;
                T[(cc + 1) * TS + r]     = acc[mi][ni][1] * alpha;
                T[cc * TS + r + 8]       = acc[mi][ni][2] * alpha;
                T[(cc + 1) * TS + r + 8] = acc[mi][ni][3] * alpha;
            }
        }
        __syncthreads();
        const int b  = rowBase / SEQ;
        const int n0 = rowBase - b * SEQ;
        const int cl = tid >> 6;        // 0..3
        const int rw = tid & 63;        // 0..63
#pragma unroll 4
        for (int cc = cl; cc < 128; cc += 4) {
            float x0 = T[cc * TS + 2 * rw];
            float x1 = T[cc * TS + 2 * rw + 1];
            uint32_t wh, wl;
            split_pair(x0, x1, wh, wl);
            const long o = ((long)b * EMB + colBase + cc) * (SEQ / 2) +
                           (n0 >> 1) + rw;
            Ch[o] = wh;
            Cl[o] = wl;
        }
    }
}

// ---------------------------------------------------------------------------
// Row softmax (in place on f32) + linear bf16 split side outputs.
// ---------------------------------------------------------------------------
__global__ void __launch_bounds__(256) softmax_rows(
    float* __restrict__ attn, uint32_t* __restrict__ hi,
    uint32_t* __restrict__ lo)
{
    const long row = blockIdx.x;
    float* p = attn + row * SEQ;
    uint32_t* hb = hi + row * (SEQ / 2);
    uint32_t* lb = lo + row * (SEQ / 2);
    const int tid  = threadIdx.x;
    const int lane = tid & 31;
    const int wid  = tid >> 5;
    __shared__ float red[8];

    float2 vals[4];
    float lmax = -INFINITY;
#pragma unroll
    for (int i = 0; i < 4; i++) {
        vals[i] = *(const float2*)(p + 2 * (tid + i * 256));
        lmax = fmaxf(lmax, fmaxf(vals[i].x, vals[i].y));
    }
#pragma unroll
    for (int o = 16; o > 0; o >>= 1)
        lmax = fmaxf(lmax, __shfl_xor_sync(0xFFFFFFFFu, lmax, o));
    if (lane == 0) red[wid] = lmax;
    __syncthreads();
    float m = red[0];
#pragma unroll
    for (int w = 1; w < 8; w++) m = fmaxf(m, red[w]);
    __syncthreads();   // protect red[] before reuse for the sum

    float lsum = 0.f;
#pragma unroll
    for (int i = 0; i < 4; i++) {
        vals[i].x = __expf(vals[i].x - m);
        vals[i].y = __expf(vals[i].y - m);
        lsum += vals[i].x + vals[i].y;
    }
#pragma unroll
    for (int o = 16; o > 0; o >>= 1)
        lsum += __shfl_xor_sync(0xFFFFFFFFu, lsum, o);
    if (lane == 0) red[wid] = lsum;
    __syncthreads();
    float tot = red[0];
#pragma unroll
    for (int w = 1; w < 8; w++) tot += red[w];

    const float inv = 1.f / tot;
#pragma unroll
    for (int i = 0; i < 4; i++) {
        const int w = tid + i * 256;
        float2 o2 = make_float2(vals[i].x * inv, vals[i].y * inv);
        *(float2*)(p + 2 * w) = o2;
        uint32_t wh, wl;
        split_pair(o2.x, o2.y, wh, wl);
        hb[w] = wh;
        lb[w] = wl;
    }
}

// ---------------------------------------------------------------------------
extern "C" void kernel_launch(void* const* d_in, const int* in_sizes, int n_in,
                              void* d_out, int out_size)
{
    const float* q  = (const float*)d_in[0];
    const float* k  = (const float*)d_in[1];
    const float* v  = (const float*)d_in[2];
    const float* Wq = (const float*)d_in[3];
    const float* Wk = (const float*)d_in[4];
    const float* Wv = (const float*)d_in[5];

    float* out  = (float*)d_out;                  // [B, N, E]
    float* attn = out + (long)BATCH * SEQ * EMB;  // [B, N, N]

    uint32_t *qh, *ql, *kh, *kl, *vh, *vl;
    uint32_t *Wqh, *Wql, *Wkh, *Wkl, *Wvh, *Wvl;
    uint32_t *qph, *qpl, *kph, *kpl, *vpth, *vptl, *ath, *atl;
    cudaGetSymbolAddress((void**)&qh,  g_qh);   cudaGetSymbolAddress((void**)&ql,  g_ql);
    cudaGetSymbolAddress((void**)&kh,  g_kh);   cudaGetSymbolAddress((void**)&kl,  g_kl);
    cudaGetSymbolAddress((void**)&vh,  g_vh);   cudaGetSymbolAddress((void**)&vl,  g_vl);
    cudaGetSymbolAddress((void**)&Wqh, g_Wqh);  cudaGetSymbolAddress((void**)&Wql, g_Wql);
    cudaGetSymbolAddress((void**)&Wkh, g_Wkh);  cudaGetSymbolAddress((void**)&Wkl, g_Wkl);
    cudaGetSymbolAddress((void**)&Wvh, g_Wvh);  cudaGetSymbolAddress((void**)&Wvl, g_Wvl);
    cudaGetSymbolAddress((void**)&qph, g_qph);  cudaGetSymbolAddress((void**)&qpl, g_qpl);
    cudaGetSymbolAddress((void**)&kph, g_kph);  cudaGetSymbolAddress((void**)&kpl, g_kpl);
    cudaGetSymbolAddress((void**)&vpth, g_vpth); cudaGetSymbolAddress((void**)&vptl, g_vptl);
    cudaGetSymbolAddress((void**)&ath, g_ath);  cudaGetSymbolAddress((void**)&atl, g_atl);

    cudaFuncSetAttribute(gemm_bs<0>, cudaFuncAttributeMaxDynamicSharedMemorySize, SMEM_BYTES);
    cudaFuncSetAttribute(gemm_bs<1>, cudaFuncAttributeMaxDynamicSharedMemorySize, SMEM_BYTES);
    cudaFuncSetAttribute(gemm_bs<2>, cudaFuncAttributeMaxDynamicSharedMemorySize, SMEM_BYTES);

    const float c = 0.044194173824159216f;  // 1/sqrt(512)

    // 1) split all inputs in one launch
    const long inWords = (long)BATCH * SEQ * DIM / 2;
    const long wWords  = (long)EMB * DIM / 2;
    const long totW = 3 * inWords + 3 * wWords;
    convert_all<<<(unsigned)((totW + 255) / 256), 256>>>(
        q, k, v, Wq, Wk, Wv,
        qh, ql, kh, kl, vh, vl,
        Wqh, Wql, Wkh, Wkl, Wvh, Wvl, inWords, wWords);

    // 2) projections  (M = B*N, N = EMB, K = DIM)
    dim3 gp(EMB / 128, (BATCH * SEQ) / 128, 1);
    gemm_bs<1><<<gp, 256, SMEM_BYTES>>>(qh, ql, Wqh, Wql, nullptr, qph, qpl,
                                        BATCH * SEQ, EMB, DIM, c, 0, 0, 0);
    gemm_bs<1><<<gp, 256, SMEM_BYTES>>>(kh, kl, Wkh, Wkl, nullptr, kph, kpl,
                                        BATCH * SEQ, EMB, DIM, c, 0, 0, 0);
    // v projection writes TRANSPOSED split planes directly (EPI=2)
    gemm_bs<2><<<gp, 256, SMEM_BYTES>>>(vh, vl, Wvh, Wvl, nullptr, vpth, vptl,
                                        BATCH * SEQ, EMB, DIM, c, 0, 0, 0);

    // 3) dots = qp @ kp^T * c -> attn (f32)
    dim3 gd(SEQ / 128, SEQ / 128, BATCH);
    gemm_bs<0><<<gd, 256, SMEM_BYTES>>>(qph, qpl, kph, kpl, attn, nullptr, nullptr,
                                        SEQ, SEQ, EMB, c,
                                        (long)SEQ * EMB / 2, (long)SEQ * EMB / 2,
                                        (long)SEQ * SEQ);

    // 4) softmax (f32 in place + split planes)
    softmax_rows<<<BATCH * SEQ, 256>>>(attn, ath, atl);

    // 5) out = attn @ vpt^T
    dim3 go(EMB / 128, SEQ / 128, BATCH);
    gemm_bs<0><<<go, 256, SMEM_BYTES>>>(ath, atl, vpth, vptl, out, nullptr, nullptr,
                                        SEQ, EMB, SEQ, 1.0f,
                                        (long)SEQ * SEQ / 2, (long)SEQ * EMB / 2,
                                        (long)SEQ * EMB);
}